// round 1
// baseline (speedup 1.0000x reference)
#include <cuda_runtime.h>
#include <cstdint>
#include <cmath>

// Problem constants
#define BB   128
#define LL   400
#define TT   30
#define EE   300
#define HE   512
#define HD   512
#define AA   512
#define VV   20000
#define PAD_ID 0
#define UNK_ID 1
#define SOS_ID 2

// ---------------------------------------------------------------------------
// Scratch (device globals; no runtime allocation allowed)
// ---------------------------------------------------------------------------
__device__ float g_enc_proj[(size_t)BB * LL * AA];   // 105 MB
__device__ float g_gi[BB * 3 * HD];
__device__ float g_gh[BB * 3 * HD];
__device__ float g_s0[BB * HD];
__device__ float g_s1[BB * HD];
__device__ float g_c0[BB * HE];
__device__ float g_c1[BB * HE];
__device__ float g_q[BB * AA];
__device__ float g_attn[BB * LL];
__device__ float g_pc[BB];
__device__ float g_rvec[BB * HD];
__device__ float g_energy[BB * VV];                  // 10.2 MB

// ---------------------------------------------------------------------------
// Helpers
// ---------------------------------------------------------------------------
__device__ __forceinline__ uint32_t f2tf32(float x) {
    uint32_t r;
    asm("cvt.rna.tf32.f32 %0, %1;" : "=r"(r) : "f"(x));
    return r;
}

__device__ __forceinline__ void mma_tf32(float (&c)[4], const uint32_t (&a)[4],
                                         const uint32_t (&b)[2]) {
    asm volatile(
        "mma.sync.aligned.m16n8k8.row.col.f32.tf32.tf32.f32 "
        "{%0,%1,%2,%3}, {%4,%5,%6,%7}, {%8,%9}, {%0,%1,%2,%3};\n"
        : "+f"(c[0]), "+f"(c[1]), "+f"(c[2]), "+f"(c[3])
        : "r"(a[0]), "r"(a[1]), "r"(a[2]), "r"(a[3]), "r"(b[0]), "r"(b[1]));
}

__device__ __forceinline__ float warpMax(float v) {
    #pragma unroll
    for (int o = 16; o; o >>= 1) v = fmaxf(v, __shfl_xor_sync(0xffffffffu, v, o));
    return v;
}
__device__ __forceinline__ float warpSum(float v) {
    #pragma unroll
    for (int o = 16; o; o >>= 1) v += __shfl_xor_sync(0xffffffffu, v, o);
    return v;
}

__device__ __forceinline__ float blockMax(float v, float* red) {
    v = warpMax(v);
    int w = threadIdx.x >> 5, l = threadIdx.x & 31, nw = blockDim.x >> 5;
    if (l == 0) red[w] = v;
    __syncthreads();
    if (threadIdx.x < 32) {
        float x = (threadIdx.x < nw) ? red[threadIdx.x] : -INFINITY;
        x = warpMax(x);
        if (threadIdx.x == 0) red[0] = x;
    }
    __syncthreads();
    v = red[0];
    __syncthreads();
    return v;
}
__device__ __forceinline__ float blockSum(float v, float* red) {
    v = warpSum(v);
    int w = threadIdx.x >> 5, l = threadIdx.x & 31, nw = blockDim.x >> 5;
    if (l == 0) red[w] = v;
    __syncthreads();
    if (threadIdx.x < 32) {
        float x = (threadIdx.x < nw) ? red[threadIdx.x] : 0.0f;
        x = warpSum(x);
        if (threadIdx.x == 0) red[0] = x;
    }
    __syncthreads();
    v = red[0];
    __syncthreads();
    return v;
}

__device__ __forceinline__ float sigmoidf_(float x) {
    return 1.0f / (1.0f + expf(-x));
}

// ---------------------------------------------------------------------------
// Generic skinny GEMM: C[M,N] = A[M,K] @ W[N,K]^T (+bias), tf32 tensor cores.
// A-side loader modes fuse the gather/concat/maxout stages (saves kernels).
// ---------------------------------------------------------------------------
struct GArgs {
    const float* A; int lda;
    const float* W;
    float* C; int ldc;
    const float* bias;
    int M, N, K;
    // loader extras
    const float* embed;   // [V, E]
    const int*   tgt;     // [B, T]
    int          t;
    const float* ctx;     // [B, HE]
    const float* s;       // [B, HD]
};

#define MODE_PLAIN  0
#define MODE_X      1   // [embed[word], ctx_prev]              K = E+HE = 812
#define MODE_XR     2   // [embed[word], ctx_new, s_new]        K = 1324
#define MODE_MAXOUT 3   // max(rvec[m][2k], rvec[m][2k+1])      K = 256

__device__ __forceinline__ int word_of(const GArgs& g, int m) {
    if (g.t == 0) return SOS_ID;
    int w = g.tgt[m * TT + g.t - 1];
    return (w >= VV) ? UNK_ID : w;
}

template <int MODE>
__device__ __forceinline__ float loadA(const GArgs& g, int m, int k) {
    if (MODE == MODE_PLAIN) {
        return g.A[(size_t)m * g.lda + k];
    } else if (MODE == MODE_X) {
        if (k < EE) {
            int w = word_of(g, m);
            return g.embed[(size_t)w * EE + k];
        }
        return g.ctx[m * HE + (k - EE)];
    } else if (MODE == MODE_XR) {
        if (k < EE) {
            int w = word_of(g, m);
            return g.embed[(size_t)w * EE + k];
        }
        if (k < EE + HE) return g.ctx[m * HE + (k - EE)];
        return g.s[m * HD + (k - EE - HE)];
    } else { // MODE_MAXOUT
        float a = g.A[m * HD + 2 * k];
        float b = g.A[m * HD + 2 * k + 1];
        return fmaxf(a, b);
    }
}

template <int MODE>
__global__ __launch_bounds__(256) void gemm_kernel(GArgs g) {
    __shared__ uint32_t As[64][17];
    __shared__ uint32_t Ws[64][17];

    const int tid  = threadIdx.x;
    const int lane = tid & 31;
    const int warp = tid >> 5;
    const int gid  = lane >> 2;     // 0..7
    const int tig  = lane & 3;      // 0..3
    const int wm   = warp >> 2;     // 0..1
    const int wn   = warp & 3;      // 0..3
    const int mt0  = blockIdx.y * 64;
    const int nt0  = blockIdx.x * 64;

    float c[2][2][4] = {};

    const int row = tid >> 2;            // 0..63 (tile row for loading)
    const int kq  = (tid & 3) << 2;      // 0,4,8,12

    for (int k0 = 0; k0 < g.K; k0 += 16) {
        __syncthreads();
        {
            int gm = mt0 + row;
            #pragma unroll
            for (int i = 0; i < 4; i++) {
                int k = k0 + kq + i;
                float v = (k < g.K) ? loadA<MODE>(g, gm, k) : 0.0f;
                As[row][kq + i] = f2tf32(v);
            }
            int gn = nt0 + row;
            const float* wr = g.W + (size_t)gn * g.K;
            #pragma unroll
            for (int i = 0; i < 4; i++) {
                int k = k0 + kq + i;
                float v = (k < g.K && gn < g.N) ? wr[k] : 0.0f;
                Ws[row][kq + i] = f2tf32(v);
            }
        }
        __syncthreads();

        #pragma unroll
        for (int k8 = 0; k8 < 16; k8 += 8) {
            uint32_t a[2][4], bfr[2][2];
            #pragma unroll
            for (int mt = 0; mt < 2; mt++) {
                int r0 = wm * 32 + mt * 16 + gid;
                a[mt][0] = As[r0][k8 + tig];
                a[mt][1] = As[r0 + 8][k8 + tig];
                a[mt][2] = As[r0][k8 + 4 + tig];
                a[mt][3] = As[r0 + 8][k8 + 4 + tig];
            }
            #pragma unroll
            for (int nt = 0; nt < 2; nt++) {
                int n0 = wn * 16 + nt * 8 + gid;
                bfr[nt][0] = Ws[n0][k8 + tig];
                bfr[nt][1] = Ws[n0][k8 + 4 + tig];
            }
            #pragma unroll
            for (int mt = 0; mt < 2; mt++)
                #pragma unroll
                for (int nt = 0; nt < 2; nt++)
                    mma_tf32(c[mt][nt], a[mt], bfr[nt]);
        }
    }

    // Epilogue (M is always a multiple of 64 here; guard N only)
    #pragma unroll
    for (int mt = 0; mt < 2; mt++) {
        #pragma unroll
        for (int nt = 0; nt < 2; nt++) {
            int r  = mt0 + wm * 32 + mt * 16 + gid;
            int cn = nt0 + wn * 16 + nt * 8 + 2 * tig;
            if (cn < g.N) {
                float bb = g.bias ? g.bias[cn] : 0.0f;
                g.C[(size_t)r * g.ldc + cn]       = c[mt][nt][0] + bb;
                g.C[(size_t)(r + 8) * g.ldc + cn] = c[mt][nt][2] + bb;
            }
            if (cn + 1 < g.N) {
                float bb = g.bias ? g.bias[cn + 1] : 0.0f;
                g.C[(size_t)r * g.ldc + cn + 1]       = c[mt][nt][1] + bb;
                g.C[(size_t)(r + 8) * g.ldc + cn + 1] = c[mt][nt][3] + bb;
            }
        }
    }
}

// ---------------------------------------------------------------------------
// GRU elementwise update: s_new = (1-z)*n + z*s
// ---------------------------------------------------------------------------
__global__ __launch_bounds__(256) void gru_kernel(
    const float* __restrict__ gi, const float* __restrict__ gh,
    const float* __restrict__ b_ih, const float* __restrict__ b_hh,
    const float* __restrict__ s_old, float* __restrict__ s_new)
{
    int idx = blockIdx.x * blockDim.x + threadIdx.x;   // BB*HD threads
    int b = idx >> 9, h = idx & 511;
    const float* gib = gi + (size_t)b * 3 * HD;
    const float* ghb = gh + (size_t)b * 3 * HD;
    float ir = gib[h]            + b_ih[h];
    float iz = gib[HD + h]       + b_ih[HD + h];
    float in = gib[2 * HD + h]   + b_ih[2 * HD + h];
    float hr = ghb[h]            + b_hh[h];
    float hz = ghb[HD + h]       + b_hh[HD + h];
    float hn = ghb[2 * HD + h]   + b_hh[2 * HD + h];
    float r = sigmoidf_(ir + hr);
    float z = sigmoidf_(iz + hz);
    float n = tanhf(in + r * hn);
    float so = s_old[idx];
    s_new[idx] = (1.0f - z) * n + z * so;
}

// ---------------------------------------------------------------------------
// Fused attention: e -> masked softmax -> ctx -> p_copy. One block per b.
// ---------------------------------------------------------------------------
__global__ __launch_bounds__(512) void attn_ctx_kernel(
    const float* __restrict__ q,      // [B, A] (bias already added)
    const float* __restrict__ proj,   // [B, L, A]
    const float* __restrict__ enc,    // [B, L, HE]
    const float* __restrict__ vvec,   // [A]
    const int*   __restrict__ src,    // [B, L]
    const float* __restrict__ s_new,  // [B, HD]
    const float* __restrict__ copy_W, // [1, HD+HE]
    const float* __restrict__ copy_b, // [1]
    float* __restrict__ attn_out,     // [B, L]
    float* __restrict__ ctx_out,      // [B, HE]
    float* __restrict__ pc_out)       // [B]
{
    __shared__ float qs[AA];
    __shared__ float vs[AA];
    __shared__ float es[LL];
    __shared__ float red[32];

    int b = blockIdx.x, tid = threadIdx.x;
    qs[tid] = q[b * AA + tid];
    vs[tid] = vvec[tid];
    __syncthreads();

    int warp = tid >> 5, lane = tid & 31;
    // Phase 1: scores e[l]
    for (int l = warp; l < LL; l += 16) {
        const float* pp = proj + ((size_t)b * LL + l) * AA;
        float acc = 0.0f;
        #pragma unroll 4
        for (int i = lane; i < AA; i += 32)
            acc += tanhf(pp[i] + qs[i]) * vs[i];
        acc = warpSum(acc);
        if (lane == 0)
            es[l] = (src[b * LL + l] == PAD_ID) ? -1e30f : acc;
    }
    __syncthreads();

    // Phase 2: softmax over L
    float ev = (tid < LL) ? es[tid] : -INFINITY;
    float m  = blockMax(ev, red);
    float p  = (tid < LL) ? expf(ev - m) : 0.0f;
    float Z  = blockSum(p, red);
    float a  = p / Z;
    if (tid < LL) { es[tid] = a; attn_out[b * LL + tid] = a; }
    __syncthreads();

    // Phase 3: ctx[e] = sum_l attn[l] * enc[b,l,e]
    float a0 = 0, a1 = 0, a2 = 0, a3 = 0;
    const float* eb = enc + (size_t)b * LL * HE + tid;
    #pragma unroll 4
    for (int l = 0; l < LL; l += 4) {
        a0 += es[l]     * eb[(size_t)(l)     * HE];
        a1 += es[l + 1] * eb[(size_t)(l + 1) * HE];
        a2 += es[l + 2] * eb[(size_t)(l + 2) * HE];
        a3 += es[l + 3] * eb[(size_t)(l + 3) * HE];
    }
    float ctxv = (a0 + a1) + (a2 + a3);
    ctx_out[b * HE + tid] = ctxv;

    // Phase 4: p_copy = sigmoid([s_new, ctx] . copy_W + copy_b)
    float part = s_new[b * HD + tid] * copy_W[tid] + ctxv * copy_W[HD + tid];
    float tot = blockSum(part, red);
    if (tid == 0) pc_out[b] = sigmoidf_(tot + copy_b[0]);
}

// ---------------------------------------------------------------------------
// Output: softmax over V, log of [(1-pc)*p_vocab, pc*attn] + 1e-12
// ---------------------------------------------------------------------------
__global__ __launch_bounds__(1024) void output_kernel(
    const float* __restrict__ energy,  // [B, V]
    const float* __restrict__ attn,    // [B, L]
    const float* __restrict__ pc_in,   // [B]
    float* __restrict__ out, int t)
{
    __shared__ float red[32];
    int b = blockIdx.x, tid = threadIdx.x;
    const float* eb = energy + (size_t)b * VV;

    float mx = -INFINITY;
    for (int j = tid; j < VV; j += 1024) mx = fmaxf(mx, eb[j]);
    mx = blockMax(mx, red);

    float sum = 0.0f;
    for (int j = tid; j < VV; j += 1024) sum += expf(eb[j] - mx);
    sum = blockSum(sum, red);

    float pc = pc_in[b];
    float scale = (1.0f - pc) / sum;
    float* ob = out + ((size_t)b * TT + t) * (VV + LL);
    for (int j = tid; j < VV; j += 1024)
        ob[j] = logf(fmaf(expf(eb[j] - mx), scale, 1e-12f));
    for (int j = tid; j < LL; j += 1024)
        ob[VV + j] = logf(fmaf(pc, attn[b * LL + j], 1e-12f));
}

// ---------------------------------------------------------------------------
// Host orchestration
// ---------------------------------------------------------------------------
extern "C" void kernel_launch(void* const* d_in, const int* in_sizes, int n_in,
                              void* d_out, int out_size)
{
    const float* enc     = (const float*)d_in[0];
    const float* s_in    = (const float*)d_in[1];
    const int*   src     = (const int*)  d_in[2];
    const int*   tgt     = (const int*)  d_in[3];
    const float* embed   = (const float*)d_in[4];
    const float* W_ih    = (const float*)d_in[5];
    const float* b_ih    = (const float*)d_in[6];
    const float* W_hh    = (const float*)d_in[7];
    const float* b_hh    = (const float*)d_in[8];
    const float* att_Wh  = (const float*)d_in[9];
    const float* att_Ws  = (const float*)d_in[10];
    const float* att_b   = (const float*)d_in[11];
    const float* att_v   = (const float*)d_in[12];
    const float* copy_W  = (const float*)d_in[13];
    const float* copy_b  = (const float*)d_in[14];
    const float* read_W  = (const float*)d_in[15];
    const float* read_b  = (const float*)d_in[16];
    const float* read_Wo = (const float*)d_in[17];
    float* out = (float*)d_out;

    float *p_proj, *p_gi, *p_gh, *p_s0, *p_s1, *p_c0, *p_c1;
    float *p_q, *p_attn, *p_pc, *p_rvec, *p_energy;
    cudaGetSymbolAddress((void**)&p_proj,   g_enc_proj);
    cudaGetSymbolAddress((void**)&p_gi,     g_gi);
    cudaGetSymbolAddress((void**)&p_gh,     g_gh);
    cudaGetSymbolAddress((void**)&p_s0,     g_s0);
    cudaGetSymbolAddress((void**)&p_s1,     g_s1);
    cudaGetSymbolAddress((void**)&p_c0,     g_c0);
    cudaGetSymbolAddress((void**)&p_c1,     g_c1);
    cudaGetSymbolAddress((void**)&p_q,      g_q);
    cudaGetSymbolAddress((void**)&p_attn,   g_attn);
    cudaGetSymbolAddress((void**)&p_pc,     g_pc);
    cudaGetSymbolAddress((void**)&p_rvec,   g_rvec);
    cudaGetSymbolAddress((void**)&p_energy, g_energy);

    // init recurrent state
    cudaMemcpyAsync(p_s0, s_in, BB * HD * sizeof(float),
                    cudaMemcpyDeviceToDevice, 0);
    cudaMemsetAsync(p_c0, 0, BB * HE * sizeof(float), 0);

    // enc_proj = enc_outputs @ att_Wh^T  (once)
    {
        GArgs g{};
        g.A = enc; g.lda = HE; g.W = att_Wh;
        g.C = p_proj; g.ldc = AA; g.bias = nullptr;
        g.M = BB * LL; g.N = AA; g.K = HE;
        gemm_kernel<MODE_PLAIN><<<dim3(AA / 64, (BB * LL) / 64), 256>>>(g);
    }

    float* sbuf[2] = {p_s0, p_s1};
    float* cbuf[2] = {p_c0, p_c1};

    for (int t = 0; t < TT; t++) {
        float* s_cur = sbuf[t & 1];
        float* s_nx  = sbuf[(t + 1) & 1];
        float* c_cur = cbuf[t & 1];
        float* c_nx  = cbuf[(t + 1) & 1];

        // gi = [emb, ctx] @ W_ih^T
        {
            GArgs g{};
            g.W = W_ih; g.C = p_gi; g.ldc = 3 * HD; g.bias = nullptr;
            g.M = BB; g.N = 3 * HD; g.K = EE + HE;
            g.embed = embed; g.tgt = tgt; g.t = t; g.ctx = c_cur;
            gemm_kernel<MODE_X><<<dim3((3 * HD) / 64, BB / 64), 256>>>(g);
        }
        // gh = s @ W_hh^T
        {
            GArgs g{};
            g.A = s_cur; g.lda = HD; g.W = W_hh;
            g.C = p_gh; g.ldc = 3 * HD; g.bias = nullptr;
            g.M = BB; g.N = 3 * HD; g.K = HD;
            gemm_kernel<MODE_PLAIN><<<dim3((3 * HD) / 64, BB / 64), 256>>>(g);
        }
        gru_kernel<<<(BB * HD) / 256, 256>>>(p_gi, p_gh, b_ih, b_hh, s_cur, s_nx);

        // q = s_new @ att_Ws^T + att_b
        {
            GArgs g{};
            g.A = s_nx; g.lda = HD; g.W = att_Ws;
            g.C = p_q; g.ldc = AA; g.bias = att_b;
            g.M = BB; g.N = AA; g.K = HD;
            gemm_kernel<MODE_PLAIN><<<dim3(AA / 64, BB / 64), 256>>>(g);
        }

        attn_ctx_kernel<<<BB, 512>>>(p_q, p_proj, enc, att_v, src, s_nx,
                                     copy_W, copy_b, p_attn, c_nx, p_pc);

        // rvec = [emb, ctx_new, s_new] @ read_W^T + read_b
        {
            GArgs g{};
            g.W = read_W; g.C = p_rvec; g.ldc = HD; g.bias = read_b;
            g.M = BB; g.N = HD; g.K = EE + HE + HD;
            g.embed = embed; g.tgt = tgt; g.t = t; g.ctx = c_nx; g.s = s_nx;
            gemm_kernel<MODE_XR><<<dim3(HD / 64, BB / 64), 256>>>(g);
        }
        // energy = maxout(rvec) @ read_Wo^T
        {
            GArgs g{};
            g.A = p_rvec; g.W = read_Wo;
            g.C = p_energy; g.ldc = VV; g.bias = nullptr;
            g.M = BB; g.N = VV; g.K = HD / 2;
            gemm_kernel<MODE_MAXOUT><<<dim3((VV + 63) / 64, BB / 64), 256>>>(g);
        }

        output_kernel<<<BB, 1024>>>(p_energy, p_attn, p_pc, out, t);
    }
}

// round 2
// speedup vs baseline: 1.0019x; 1.0019x over previous
#include <cuda_runtime.h>
#include <cstdint>
#include <cmath>

// Problem constants
#define BB   128
#define LL   400
#define TT   30
#define EE   300
#define HE   512
#define HD   512
#define AA   512
#define VV   20000
#define PAD_ID 0
#define UNK_ID 1
#define SOS_ID 2

// ---------------------------------------------------------------------------
// Scratch (device globals; no runtime allocation allowed)
// ---------------------------------------------------------------------------
__device__ float g_enc_proj[(size_t)BB * LL * AA];   // 105 MB
__device__ float g_gi[BB * 3 * HD];
__device__ float g_gh[BB * 3 * HD];
__device__ float g_s0[BB * HD];
__device__ float g_s1[BB * HD];
__device__ float g_c0[BB * HE];
__device__ float g_c1[BB * HE];
__device__ float g_q[BB * AA];
__device__ float g_attn[BB * LL];
__device__ float g_pc[BB];
__device__ float g_rvec[BB * HD];
__device__ float g_energy[BB * VV];                  // 10.2 MB

// ---------------------------------------------------------------------------
// Helpers
// ---------------------------------------------------------------------------
__device__ __forceinline__ uint32_t f2tf32(float x) {
    uint32_t r;
    asm("cvt.rna.tf32.f32 %0, %1;" : "=r"(r) : "f"(x));
    return r;
}

__device__ __forceinline__ void mma_tf32(float (&c)[4], const uint32_t (&a)[4],
                                         const uint32_t (&b)[2]) {
    asm volatile(
        "mma.sync.aligned.m16n8k8.row.col.f32.tf32.tf32.f32 "
        "{%0,%1,%2,%3}, {%4,%5,%6,%7}, {%8,%9}, {%0,%1,%2,%3};\n"
        : "+f"(c[0]), "+f"(c[1]), "+f"(c[2]), "+f"(c[3])
        : "r"(a[0]), "r"(a[1]), "r"(a[2]), "r"(a[3]), "r"(b[0]), "r"(b[1]));
}

__device__ __forceinline__ float warpMax(float v) {
    #pragma unroll
    for (int o = 16; o; o >>= 1) v = fmaxf(v, __shfl_xor_sync(0xffffffffu, v, o));
    return v;
}
__device__ __forceinline__ float warpSum(float v) {
    #pragma unroll
    for (int o = 16; o; o >>= 1) v += __shfl_xor_sync(0xffffffffu, v, o);
    return v;
}

__device__ __forceinline__ float blockMax(float v, float* red) {
    v = warpMax(v);
    int w = threadIdx.x >> 5, l = threadIdx.x & 31, nw = blockDim.x >> 5;
    if (l == 0) red[w] = v;
    __syncthreads();
    if (threadIdx.x < 32) {
        float x = (threadIdx.x < nw) ? red[threadIdx.x] : -INFINITY;
        x = warpMax(x);
        if (threadIdx.x == 0) red[0] = x;
    }
    __syncthreads();
    v = red[0];
    __syncthreads();
    return v;
}
__device__ __forceinline__ float blockSum(float v, float* red) {
    v = warpSum(v);
    int w = threadIdx.x >> 5, l = threadIdx.x & 31, nw = blockDim.x >> 5;
    if (l == 0) red[w] = v;
    __syncthreads();
    if (threadIdx.x < 32) {
        float x = (threadIdx.x < nw) ? red[threadIdx.x] : 0.0f;
        x = warpSum(x);
        if (threadIdx.x == 0) red[0] = x;
    }
    __syncthreads();
    v = red[0];
    __syncthreads();
    return v;
}

__device__ __forceinline__ float sigmoidf_(float x) {
    return 1.0f / (1.0f + expf(-x));
}

// ---------------------------------------------------------------------------
// Generic skinny GEMM: C[M,N] = A[M,K] @ W[N,K]^T (+bias), tf32 tensor cores.
// A-side loader modes fuse the gather/concat/maxout stages (saves kernels).
// ---------------------------------------------------------------------------
struct GArgs {
    const float* A; int lda;
    const float* W;
    float* C; int ldc;
    const float* bias;
    int M, N, K;
    // loader extras
    const float* embed;   // [V, E]
    const int*   tgt;     // [B, T]
    int          t;
    const float* ctx;     // [B, HE]
    const float* s;       // [B, HD]
};

#define MODE_PLAIN  0
#define MODE_X      1   // [embed[word], ctx_prev]              K = E+HE = 812
#define MODE_XR     2   // [embed[word], ctx_new, s_new]        K = 1324
#define MODE_MAXOUT 3   // max(rvec[m][2k], rvec[m][2k+1])      K = 256

__device__ __forceinline__ int word_of(const GArgs& g, int m) {
    if (g.t == 0) return SOS_ID;
    int w = g.tgt[m * TT + g.t - 1];
    return (w >= VV) ? UNK_ID : w;
}

template <int MODE>
__device__ __forceinline__ float loadA(const GArgs& g, int m, int k) {
    if (MODE == MODE_PLAIN) {
        return g.A[(size_t)m * g.lda + k];
    } else if (MODE == MODE_X) {
        if (k < EE) {
            int w = word_of(g, m);
            return g.embed[(size_t)w * EE + k];
        }
        return g.ctx[m * HE + (k - EE)];
    } else if (MODE == MODE_XR) {
        if (k < EE) {
            int w = word_of(g, m);
            return g.embed[(size_t)w * EE + k];
        }
        if (k < EE + HE) return g.ctx[m * HE + (k - EE)];
        return g.s[m * HD + (k - EE - HE)];
    } else { // MODE_MAXOUT
        float a = g.A[m * HD + 2 * k];
        float b = g.A[m * HD + 2 * k + 1];
        return fmaxf(a, b);
    }
}

template <int MODE>
__global__ __launch_bounds__(256) void gemm_kernel(GArgs g) {
    __shared__ uint32_t As[64][17];
    __shared__ uint32_t Ws[64][17];

    const int tid  = threadIdx.x;
    const int lane = tid & 31;
    const int warp = tid >> 5;
    const int gid  = lane >> 2;     // 0..7
    const int tig  = lane & 3;      // 0..3
    const int wm   = warp >> 2;     // 0..1
    const int wn   = warp & 3;      // 0..3
    const int mt0  = blockIdx.y * 64;
    const int nt0  = blockIdx.x * 64;

    float c[2][2][4] = {};

    const int row = tid >> 2;            // 0..63 (tile row for loading)
    const int kq  = (tid & 3) << 2;      // 0,4,8,12

    for (int k0 = 0; k0 < g.K; k0 += 16) {
        __syncthreads();
        {
            int gm = mt0 + row;
            #pragma unroll
            for (int i = 0; i < 4; i++) {
                int k = k0 + kq + i;
                float v = (k < g.K) ? loadA<MODE>(g, gm, k) : 0.0f;
                As[row][kq + i] = f2tf32(v);
            }
            int gn = nt0 + row;
            const float* wr = g.W + (size_t)gn * g.K;
            #pragma unroll
            for (int i = 0; i < 4; i++) {
                int k = k0 + kq + i;
                float v = (k < g.K && gn < g.N) ? wr[k] : 0.0f;
                Ws[row][kq + i] = f2tf32(v);
            }
        }
        __syncthreads();

        #pragma unroll
        for (int k8 = 0; k8 < 16; k8 += 8) {
            uint32_t a[2][4], bfr[2][2];
            #pragma unroll
            for (int mt = 0; mt < 2; mt++) {
                int r0 = wm * 32 + mt * 16 + gid;
                a[mt][0] = As[r0][k8 + tig];
                a[mt][1] = As[r0 + 8][k8 + tig];
                a[mt][2] = As[r0][k8 + 4 + tig];
                a[mt][3] = As[r0 + 8][k8 + 4 + tig];
            }
            #pragma unroll
            for (int nt = 0; nt < 2; nt++) {
                int n0 = wn * 16 + nt * 8 + gid;
                bfr[nt][0] = Ws[n0][k8 + tig];
                bfr[nt][1] = Ws[n0][k8 + 4 + tig];
            }
            #pragma unroll
            for (int mt = 0; mt < 2; mt++)
                #pragma unroll
                for (int nt = 0; nt < 2; nt++)
                    mma_tf32(c[mt][nt], a[mt], bfr[nt]);
        }
    }

    // Epilogue (M is always a multiple of 64 here; guard N only)
    #pragma unroll
    for (int mt = 0; mt < 2; mt++) {
        #pragma unroll
        for (int nt = 0; nt < 2; nt++) {
            int r  = mt0 + wm * 32 + mt * 16 + gid;
            int cn = nt0 + wn * 16 + nt * 8 + 2 * tig;
            if (cn < g.N) {
                float bb = g.bias ? g.bias[cn] : 0.0f;
                g.C[(size_t)r * g.ldc + cn]       = c[mt][nt][0] + bb;
                g.C[(size_t)(r + 8) * g.ldc + cn] = c[mt][nt][2] + bb;
            }
            if (cn + 1 < g.N) {
                float bb = g.bias ? g.bias[cn + 1] : 0.0f;
                g.C[(size_t)r * g.ldc + cn + 1]       = c[mt][nt][1] + bb;
                g.C[(size_t)(r + 8) * g.ldc + cn + 1] = c[mt][nt][3] + bb;
            }
        }
    }
}

// ---------------------------------------------------------------------------
// GRU elementwise update: s_new = (1-z)*n + z*s
// ---------------------------------------------------------------------------
__global__ __launch_bounds__(256) void gru_kernel(
    const float* __restrict__ gi, const float* __restrict__ gh,
    const float* __restrict__ b_ih, const float* __restrict__ b_hh,
    const float* __restrict__ s_old, float* __restrict__ s_new)
{
    int idx = blockIdx.x * blockDim.x + threadIdx.x;   // BB*HD threads
    int b = idx >> 9, h = idx & 511;
    const float* gib = gi + (size_t)b * 3 * HD;
    const float* ghb = gh + (size_t)b * 3 * HD;
    float ir = gib[h]            + b_ih[h];
    float iz = gib[HD + h]       + b_ih[HD + h];
    float in = gib[2 * HD + h]   + b_ih[2 * HD + h];
    float hr = ghb[h]            + b_hh[h];
    float hz = ghb[HD + h]       + b_hh[HD + h];
    float hn = ghb[2 * HD + h]   + b_hh[2 * HD + h];
    float r = sigmoidf_(ir + hr);
    float z = sigmoidf_(iz + hz);
    float n = tanhf(in + r * hn);
    float so = s_old[idx];
    s_new[idx] = (1.0f - z) * n + z * so;
}

// ---------------------------------------------------------------------------
// Fused attention: e -> masked softmax -> ctx -> p_copy. One block per b.
// ---------------------------------------------------------------------------
__global__ __launch_bounds__(512) void attn_ctx_kernel(
    const float* __restrict__ q,      // [B, A] (bias already added)
    const float* __restrict__ proj,   // [B, L, A]
    const float* __restrict__ enc,    // [B, L, HE]
    const float* __restrict__ vvec,   // [A]
    const int*   __restrict__ src,    // [B, L]
    const float* __restrict__ s_new,  // [B, HD]
    const float* __restrict__ copy_W, // [1, HD+HE]
    const float* __restrict__ copy_b, // [1]
    float* __restrict__ attn_out,     // [B, L]
    float* __restrict__ ctx_out,      // [B, HE]
    float* __restrict__ pc_out)       // [B]
{
    __shared__ float qs[AA];
    __shared__ float vs[AA];
    __shared__ float es[LL];
    __shared__ float red[32];

    int b = blockIdx.x, tid = threadIdx.x;
    qs[tid] = q[b * AA + tid];
    vs[tid] = vvec[tid];
    __syncthreads();

    int warp = tid >> 5, lane = tid & 31;
    // Phase 1: scores e[l]
    for (int l = warp; l < LL; l += 16) {
        const float* pp = proj + ((size_t)b * LL + l) * AA;
        float acc = 0.0f;
        #pragma unroll 4
        for (int i = lane; i < AA; i += 32)
            acc += tanhf(pp[i] + qs[i]) * vs[i];
        acc = warpSum(acc);
        if (lane == 0)
            es[l] = (src[b * LL + l] == PAD_ID) ? -1e30f : acc;
    }
    __syncthreads();

    // Phase 2: softmax over L
    float ev = (tid < LL) ? es[tid] : -INFINITY;
    float m  = blockMax(ev, red);
    float p  = (tid < LL) ? expf(ev - m) : 0.0f;
    float Z  = blockSum(p, red);
    float a  = p / Z;
    if (tid < LL) { es[tid] = a; attn_out[b * LL + tid] = a; }
    __syncthreads();

    // Phase 3: ctx[e] = sum_l attn[l] * enc[b,l,e]
    float a0 = 0, a1 = 0, a2 = 0, a3 = 0;
    const float* eb = enc + (size_t)b * LL * HE + tid;
    #pragma unroll 4
    for (int l = 0; l < LL; l += 4) {
        a0 += es[l]     * eb[(size_t)(l)     * HE];
        a1 += es[l + 1] * eb[(size_t)(l + 1) * HE];
        a2 += es[l + 2] * eb[(size_t)(l + 2) * HE];
        a3 += es[l + 3] * eb[(size_t)(l + 3) * HE];
    }
    float ctxv = (a0 + a1) + (a2 + a3);
    ctx_out[b * HE + tid] = ctxv;

    // Phase 4: p_copy = sigmoid([s_new, ctx] . copy_W + copy_b)
    float part = s_new[b * HD + tid] * copy_W[tid] + ctxv * copy_W[HD + tid];
    float tot = blockSum(part, red);
    if (tid == 0) pc_out[b] = sigmoidf_(tot + copy_b[0]);
}

// ---------------------------------------------------------------------------
// Output: softmax over V, log of [(1-pc)*p_vocab, pc*attn] + 1e-12
// ---------------------------------------------------------------------------
__global__ __launch_bounds__(1024) void output_kernel(
    const float* __restrict__ energy,  // [B, V]
    const float* __restrict__ attn,    // [B, L]
    const float* __restrict__ pc_in,   // [B]
    float* __restrict__ out, int t)
{
    __shared__ float red[32];
    int b = blockIdx.x, tid = threadIdx.x;
    const float* eb = energy + (size_t)b * VV;

    float mx = -INFINITY;
    for (int j = tid; j < VV; j += 1024) mx = fmaxf(mx, eb[j]);
    mx = blockMax(mx, red);

    float sum = 0.0f;
    for (int j = tid; j < VV; j += 1024) sum += expf(eb[j] - mx);
    sum = blockSum(sum, red);

    float pc = pc_in[b];
    float scale = (1.0f - pc) / sum;
    float* ob = out + ((size_t)b * TT + t) * (VV + LL);
    for (int j = tid; j < VV; j += 1024)
        ob[j] = logf(fmaf(expf(eb[j] - mx), scale, 1e-12f));
    for (int j = tid; j < LL; j += 1024)
        ob[VV + j] = logf(fmaf(pc, attn[b * LL + j], 1e-12f));
}

// ---------------------------------------------------------------------------
// Host orchestration
// ---------------------------------------------------------------------------
extern "C" void kernel_launch(void* const* d_in, const int* in_sizes, int n_in,
                              void* d_out, int out_size)
{
    const float* enc     = (const float*)d_in[0];
    const float* s_in    = (const float*)d_in[1];
    const int*   src     = (const int*)  d_in[2];
    const int*   tgt     = (const int*)  d_in[3];
    const float* embed   = (const float*)d_in[4];
    const float* W_ih    = (const float*)d_in[5];
    const float* b_ih    = (const float*)d_in[6];
    const float* W_hh    = (const float*)d_in[7];
    const float* b_hh    = (const float*)d_in[8];
    const float* att_Wh  = (const float*)d_in[9];
    const float* att_Ws  = (const float*)d_in[10];
    const float* att_b   = (const float*)d_in[11];
    const float* att_v   = (const float*)d_in[12];
    const float* copy_W  = (const float*)d_in[13];
    const float* copy_b  = (const float*)d_in[14];
    const float* read_W  = (const float*)d_in[15];
    const float* read_b  = (const float*)d_in[16];
    const float* read_Wo = (const float*)d_in[17];
    float* out = (float*)d_out;

    float *p_proj, *p_gi, *p_gh, *p_s0, *p_s1, *p_c0, *p_c1;
    float *p_q, *p_attn, *p_pc, *p_rvec, *p_energy;
    cudaGetSymbolAddress((void**)&p_proj,   g_enc_proj);
    cudaGetSymbolAddress((void**)&p_gi,     g_gi);
    cudaGetSymbolAddress((void**)&p_gh,     g_gh);
    cudaGetSymbolAddress((void**)&p_s0,     g_s0);
    cudaGetSymbolAddress((void**)&p_s1,     g_s1);
    cudaGetSymbolAddress((void**)&p_c0,     g_c0);
    cudaGetSymbolAddress((void**)&p_c1,     g_c1);
    cudaGetSymbolAddress((void**)&p_q,      g_q);
    cudaGetSymbolAddress((void**)&p_attn,   g_attn);
    cudaGetSymbolAddress((void**)&p_pc,     g_pc);
    cudaGetSymbolAddress((void**)&p_rvec,   g_rvec);
    cudaGetSymbolAddress((void**)&p_energy, g_energy);

    // init recurrent state
    cudaMemcpyAsync(p_s0, s_in, BB * HD * sizeof(float),
                    cudaMemcpyDeviceToDevice, 0);
    cudaMemsetAsync(p_c0, 0, BB * HE * sizeof(float), 0);

    // enc_proj = enc_outputs @ att_Wh^T  (once)
    {
        GArgs g{};
        g.A = enc; g.lda = HE; g.W = att_Wh;
        g.C = p_proj; g.ldc = AA; g.bias = nullptr;
        g.M = BB * LL; g.N = AA; g.K = HE;
        gemm_kernel<MODE_PLAIN><<<dim3(AA / 64, (BB * LL) / 64), 256>>>(g);
    }

    float* sbuf[2] = {p_s0, p_s1};
    float* cbuf[2] = {p_c0, p_c1};

    for (int t = 0; t < TT; t++) {
        float* s_cur = sbuf[t & 1];
        float* s_nx  = sbuf[(t + 1) & 1];
        float* c_cur = cbuf[t & 1];
        float* c_nx  = cbuf[(t + 1) & 1];

        // gi = [emb, ctx] @ W_ih^T
        {
            GArgs g{};
            g.W = W_ih; g.C = p_gi; g.ldc = 3 * HD; g.bias = nullptr;
            g.M = BB; g.N = 3 * HD; g.K = EE + HE;
            g.embed = embed; g.tgt = tgt; g.t = t; g.ctx = c_cur;
            gemm_kernel<MODE_X><<<dim3((3 * HD) / 64, BB / 64), 256>>>(g);
        }
        // gh = s @ W_hh^T
        {
            GArgs g{};
            g.A = s_cur; g.lda = HD; g.W = W_hh;
            g.C = p_gh; g.ldc = 3 * HD; g.bias = nullptr;
            g.M = BB; g.N = 3 * HD; g.K = HD;
            gemm_kernel<MODE_PLAIN><<<dim3((3 * HD) / 64, BB / 64), 256>>>(g);
        }
        gru_kernel<<<(BB * HD) / 256, 256>>>(p_gi, p_gh, b_ih, b_hh, s_cur, s_nx);

        // q = s_new @ att_Ws^T + att_b
        {
            GArgs g{};
            g.A = s_nx; g.lda = HD; g.W = att_Ws;
            g.C = p_q; g.ldc = AA; g.bias = att_b;
            g.M = BB; g.N = AA; g.K = HD;
            gemm_kernel<MODE_PLAIN><<<dim3(AA / 64, BB / 64), 256>>>(g);
        }

        attn_ctx_kernel<<<BB, 512>>>(p_q, p_proj, enc, att_v, src, s_nx,
                                     copy_W, copy_b, p_attn, c_nx, p_pc);

        // rvec = [emb, ctx_new, s_new] @ read_W^T + read_b
        {
            GArgs g{};
            g.W = read_W; g.C = p_rvec; g.ldc = HD; g.bias = read_b;
            g.M = BB; g.N = HD; g.K = EE + HE + HD;
            g.embed = embed; g.tgt = tgt; g.t = t; g.ctx = c_nx; g.s = s_nx;
            gemm_kernel<MODE_XR><<<dim3(HD / 64, BB / 64), 256>>>(g);
        }
        // energy = maxout(rvec) @ read_Wo^T
        {
            GArgs g{};
            g.A = p_rvec; g.W = read_Wo;
            g.C = p_energy; g.ldc = VV; g.bias = nullptr;
            g.M = BB; g.N = VV; g.K = HD / 2;
            gemm_kernel<MODE_MAXOUT><<<dim3((VV + 63) / 64, BB / 64), 256>>>(g);
        }

        output_kernel<<<BB, 1024>>>(p_energy, p_attn, p_pc, out, t);
    }
}

// round 3
// speedup vs baseline: 2.5984x; 2.5935x over previous
#include <cuda_runtime.h>
#include <cstdint>
#include <cmath>

// Problem constants
#define BB   128
#define LL   400
#define TT   30
#define EE   300
#define HE   512
#define HD   512
#define AA   512
#define VV   20000
#define PAD_ID 0
#define UNK_ID 1
#define SOS_ID 2

#define STAGES 4
#define PADW   20                      // smem row stride (floats), 16B-aligned, conflict-free
#define SMEM_GEMM (2 * STAGES * 64 * PADW * 4)   // 40960 bytes

// ---------------------------------------------------------------------------
// Scratch (device globals; no runtime allocation allowed)
// ---------------------------------------------------------------------------
__device__ float g_enc_proj[(size_t)BB * LL * AA];   // 105 MB
__device__ float g_gi[BB * 3 * HD];
__device__ float g_gh[BB * 3 * HD];
__device__ float g_s0[BB * HD];
__device__ float g_s1[BB * HD];
__device__ float g_c0[BB * HE];
__device__ float g_c1[BB * HE];
__device__ float g_q[BB * AA];
__device__ float g_attn[BB * LL];
__device__ float g_pc[BB];
__device__ float g_m[BB * (HD / 2)];                 // maxout output
__device__ float g_energy[BB * VV];                  // 10.2 MB

// ---------------------------------------------------------------------------
// Helpers
// ---------------------------------------------------------------------------
__device__ __forceinline__ uint32_t f2tf32(float x) {
    uint32_t r;
    asm("cvt.rna.tf32.f32 %0, %1;" : "=r"(r) : "f"(x));
    return r;
}

__device__ __forceinline__ void mma_tf32(float (&c)[4], const uint32_t (&a)[4],
                                         const uint32_t (&b)[2]) {
    asm volatile(
        "mma.sync.aligned.m16n8k8.row.col.f32.tf32.tf32.f32 "
        "{%0,%1,%2,%3}, {%4,%5,%6,%7}, {%8,%9}, {%0,%1,%2,%3};\n"
        : "+f"(c[0]), "+f"(c[1]), "+f"(c[2]), "+f"(c[3])
        : "r"(a[0]), "r"(a[1]), "r"(a[2]), "r"(a[3]), "r"(b[0]), "r"(b[1]));
}

__device__ __forceinline__ void cp_async16(uint32_t dst, const void* src, int bytes) {
    asm volatile("cp.async.ca.shared.global [%0], [%1], 16, %2;\n"
                 :: "r"(dst), "l"(src), "r"(bytes));
}
__device__ __forceinline__ void cp_commit() {
    asm volatile("cp.async.commit_group;\n" ::: "memory");
}
template <int N>
__device__ __forceinline__ void cp_wait() {
    asm volatile("cp.async.wait_group %0;\n" :: "n"(N) : "memory");
}

__device__ __forceinline__ float warpMax(float v) {
    #pragma unroll
    for (int o = 16; o; o >>= 1) v = fmaxf(v, __shfl_xor_sync(0xffffffffu, v, o));
    return v;
}
__device__ __forceinline__ float warpSum(float v) {
    #pragma unroll
    for (int o = 16; o; o >>= 1) v += __shfl_xor_sync(0xffffffffu, v, o);
    return v;
}

__device__ __forceinline__ float blockMax(float v, float* red) {
    v = warpMax(v);
    int w = threadIdx.x >> 5, l = threadIdx.x & 31, nw = blockDim.x >> 5;
    if (l == 0) red[w] = v;
    __syncthreads();
    if (threadIdx.x < 32) {
        float x = (threadIdx.x < nw) ? red[threadIdx.x] : -INFINITY;
        x = warpMax(x);
        if (threadIdx.x == 0) red[0] = x;
    }
    __syncthreads();
    v = red[0];
    __syncthreads();
    return v;
}
__device__ __forceinline__ float blockSum(float v, float* red) {
    v = warpSum(v);
    int w = threadIdx.x >> 5, l = threadIdx.x & 31, nw = blockDim.x >> 5;
    if (l == 0) red[w] = v;
    __syncthreads();
    if (threadIdx.x < 32) {
        float x = (threadIdx.x < nw) ? red[threadIdx.x] : 0.0f;
        x = warpSum(x);
        if (threadIdx.x == 0) red[0] = x;
    }
    __syncthreads();
    v = red[0];
    __syncthreads();
    return v;
}

// Fast, accurate (~1e-6) transcendentals on MUFU pipe
__device__ __forceinline__ float tanh_fast(float x) {
    x = fminf(15.0f, fmaxf(-15.0f, x));
    float e = __expf(2.0f * x);
    return 1.0f - __fdividef(2.0f, e + 1.0f);
}
__device__ __forceinline__ float sigmoid_fast(float x) {
    return __fdividef(1.0f, 1.0f + __expf(-x));
}

// ---------------------------------------------------------------------------
// Pipelined tf32 GEMM: C[M,N] = A[M,K] @ W[N,K]^T (+bias)
// ---------------------------------------------------------------------------
struct GArgs {
    const float* A; int lda;
    const float* W;
    float* C; int ldc;
    const float* bias;
    int M, N, K;
    const float* embed;   // [V, E]
    const int*   tgt;     // [B, T]
    int          t;
    const float* ctx;     // [B, HE]
    const float* s;       // [B, HD]
};

#define MODE_PLAIN 0
#define MODE_X     1   // [embed[word], ctx]            K = 812
#define MODE_XR    2   // [embed[word], ctx, s]         K = 1324

template <int MODE>
__device__ __forceinline__ const float* srcA(const GArgs& g, int m, int k, int wrd) {
    if (MODE == MODE_PLAIN) {
        return g.A + (size_t)m * g.lda + k;
    } else if (MODE == MODE_X) {
        if (k < EE) return g.embed + (size_t)wrd * EE + k;
        return g.ctx + m * HE + (k - EE);
    } else {
        if (k < EE) return g.embed + (size_t)wrd * EE + k;
        if (k < EE + HE) return g.ctx + m * HE + (k - EE);
        return g.s + m * HD + (k - EE - HE);
    }
}

template <int MODE, bool MAXOUT>
__device__ __forceinline__ void gemm_body(const GArgs& g, float* smem) {
    float* As = smem;                          // [STAGES][64][PADW]
    float* Ws = smem + STAGES * 64 * PADW;

    const int tid  = threadIdx.x;
    const int lane = tid & 31;
    const int warp = tid >> 5;
    const int gid  = lane >> 2;     // 0..7
    const int tig  = lane & 3;      // 0..3
    const int wm   = warp >> 2;     // 0..1
    const int wn   = warp & 3;      // 0..3
    const int mt0  = blockIdx.y * 64;
    const int nt0  = blockIdx.x * 64;

    const int rowL = tid >> 2;            // 0..63
    const int kq   = (tid & 3) << 2;      // 0,4,8,12

    const int gm = mt0 + rowL;
    const int gn = nt0 + rowL;
    int wrd = 0;
    if (MODE != MODE_PLAIN) {
        wrd = SOS_ID;
        if (g.t > 0) {
            int w = g.tgt[gm * TT + g.t - 1];
            wrd = (w >= VV) ? UNK_ID : w;
        }
    }

    const uint32_t aDstBase = (uint32_t)__cvta_generic_to_shared(
        &As[rowL * PADW + kq]);
    const uint32_t wDstBase = (uint32_t)__cvta_generic_to_shared(
        &Ws[rowL * PADW + kq]);
    const int stageBytes = 64 * PADW * 4;
    const bool gnOK = (gn < g.N);
    const float* wRow = g.W + (size_t)(gnOK ? gn : 0) * g.K;

    const int nk = (g.K + 15) >> 4;

    auto prefetch = [&](int i) {
        int k = i * 16 + kq;
        int buf = i & (STAGES - 1);
        bool av = (k < g.K);
        const float* ap = av ? srcA<MODE>(g, gm, k, wrd) : g.W;
        cp_async16(aDstBase + buf * stageBytes, ap, av ? 16 : 0);
        bool wv = av && gnOK;
        const float* wp = wv ? (wRow + k) : g.W;
        cp_async16(wDstBase + buf * stageBytes, wp, wv ? 16 : 0);
    };

    #pragma unroll
    for (int p = 0; p < STAGES - 1; p++) {
        if (p < nk) prefetch(p);
        cp_commit();
    }

    float c[2][2][4] = {};

    for (int i = 0; i < nk; i++) {
        if (i + STAGES - 1 < nk) prefetch(i + STAGES - 1);
        cp_commit();
        cp_wait<STAGES - 1>();
        __syncthreads();

        const float* Ab = As + (i & (STAGES - 1)) * 64 * PADW;
        const float* Wb = Ws + (i & (STAGES - 1)) * 64 * PADW;

        #pragma unroll
        for (int k8 = 0; k8 < 16; k8 += 8) {
            uint32_t a[2][4], bfr[2][2];
            #pragma unroll
            for (int mt = 0; mt < 2; mt++) {
                int r0 = wm * 32 + mt * 16 + gid;
                a[mt][0] = f2tf32(Ab[r0 * PADW + k8 + tig]);
                a[mt][1] = f2tf32(Ab[(r0 + 8) * PADW + k8 + tig]);
                a[mt][2] = f2tf32(Ab[r0 * PADW + k8 + 4 + tig]);
                a[mt][3] = f2tf32(Ab[(r0 + 8) * PADW + k8 + 4 + tig]);
            }
            #pragma unroll
            for (int nt = 0; nt < 2; nt++) {
                int n0 = wn * 16 + nt * 8 + gid;
                bfr[nt][0] = f2tf32(Wb[n0 * PADW + k8 + tig]);
                bfr[nt][1] = f2tf32(Wb[n0 * PADW + k8 + 4 + tig]);
            }
            #pragma unroll
            for (int mt = 0; mt < 2; mt++)
                #pragma unroll
                for (int nt = 0; nt < 2; nt++)
                    mma_tf32(c[mt][nt], a[mt], bfr[nt]);
        }
        __syncthreads();
    }

    // Epilogue
    #pragma unroll
    for (int mt = 0; mt < 2; mt++) {
        #pragma unroll
        for (int nt = 0; nt < 2; nt++) {
            int r  = mt0 + wm * 32 + mt * 16 + gid;
            int cn = nt0 + wn * 16 + nt * 8 + 2 * tig;
            if (MAXOUT) {
                // pairs (cn, cn+1) -> maxout column cn/2
                if (cn + 1 < g.N) {
                    float b0 = g.bias ? g.bias[cn] : 0.0f;
                    float b1 = g.bias ? g.bias[cn + 1] : 0.0f;
                    int half = cn >> 1;
                    g.C[(size_t)r * g.ldc + half] =
                        fmaxf(c[mt][nt][0] + b0, c[mt][nt][1] + b1);
                    g.C[(size_t)(r + 8) * g.ldc + half] =
                        fmaxf(c[mt][nt][2] + b0, c[mt][nt][3] + b1);
                }
            } else {
                if (cn < g.N) {
                    float bb = g.bias ? g.bias[cn] : 0.0f;
                    g.C[(size_t)r * g.ldc + cn]       = c[mt][nt][0] + bb;
                    g.C[(size_t)(r + 8) * g.ldc + cn] = c[mt][nt][2] + bb;
                }
                if (cn + 1 < g.N) {
                    float bb = g.bias ? g.bias[cn + 1] : 0.0f;
                    g.C[(size_t)r * g.ldc + cn + 1]       = c[mt][nt][1] + bb;
                    g.C[(size_t)(r + 8) * g.ldc + cn + 1] = c[mt][nt][3] + bb;
                }
            }
        }
    }
}

__global__ __launch_bounds__(256) void k_gemm_plain(GArgs g) {
    extern __shared__ float smem[];
    gemm_body<MODE_PLAIN, false>(g, smem);
}
__global__ __launch_bounds__(256) void k_gemm_xr_max(GArgs g) {
    extern __shared__ float smem[];
    gemm_body<MODE_XR, true>(g, smem);
}
// gi (MODE_X) and gh (PLAIN) fused: blockIdx.z selects
__global__ __launch_bounds__(256) void k_gates(GArgs gi, GArgs gh) {
    extern __shared__ float smem[];
    if (blockIdx.z == 0) gemm_body<MODE_X, false>(gi, smem);
    else                 gemm_body<MODE_PLAIN, false>(gh, smem);
}

// ---------------------------------------------------------------------------
// GRU elementwise update
// ---------------------------------------------------------------------------
__global__ __launch_bounds__(256) void gru_kernel(
    const float* __restrict__ gi, const float* __restrict__ gh,
    const float* __restrict__ b_ih, const float* __restrict__ b_hh,
    const float* __restrict__ s_old, float* __restrict__ s_new)
{
    int idx = blockIdx.x * blockDim.x + threadIdx.x;
    int b = idx >> 9, h = idx & 511;
    const float* gib = gi + (size_t)b * 3 * HD;
    const float* ghb = gh + (size_t)b * 3 * HD;
    float ir = gib[h]          + b_ih[h];
    float iz = gib[HD + h]     + b_ih[HD + h];
    float in = gib[2 * HD + h] + b_ih[2 * HD + h];
    float hr = ghb[h]          + b_hh[h];
    float hz = ghb[HD + h]     + b_hh[HD + h];
    float hn = ghb[2 * HD + h] + b_hh[2 * HD + h];
    float r = sigmoid_fast(ir + hr);
    float z = sigmoid_fast(iz + hz);
    float n = tanh_fast(in + r * hn);
    float so = s_old[idx];
    s_new[idx] = (1.0f - z) * n + z * so;
}

// ---------------------------------------------------------------------------
// Fused attention: e -> masked softmax -> ctx -> p_copy. One block per b.
// ---------------------------------------------------------------------------
__global__ __launch_bounds__(512) void attn_ctx_kernel(
    const float* __restrict__ q,
    const float* __restrict__ proj,
    const float* __restrict__ enc,
    const float* __restrict__ vvec,
    const int*   __restrict__ src,
    const float* __restrict__ s_new,
    const float* __restrict__ copy_W,
    const float* __restrict__ copy_b,
    float* __restrict__ attn_out,
    float* __restrict__ ctx_out,
    float* __restrict__ pc_out)
{
    __shared__ __align__(16) float es[LL];
    __shared__ float red[32];

    int b = blockIdx.x, tid = threadIdx.x;
    int warp = tid >> 5, lane = tid & 31;

    // q and v rows held in registers (float4, lane-strided)
    const float4* q4 = (const float4*)(q + (size_t)b * AA);
    const float4* v4 = (const float4*)vvec;
    float4 qv[4], vv[4];
    #pragma unroll
    for (int j = 0; j < 4; j++) { qv[j] = q4[lane + 32 * j]; vv[j] = v4[lane + 32 * j]; }

    // Phase 1: scores
    for (int l = warp; l < LL; l += 16) {
        const float4* pp = (const float4*)(proj + ((size_t)b * LL + l) * AA);
        float acc = 0.0f;
        #pragma unroll
        for (int j = 0; j < 4; j++) {
            float4 pv = pp[lane + 32 * j];
            acc += tanh_fast(pv.x + qv[j].x) * vv[j].x;
            acc += tanh_fast(pv.y + qv[j].y) * vv[j].y;
            acc += tanh_fast(pv.z + qv[j].z) * vv[j].z;
            acc += tanh_fast(pv.w + qv[j].w) * vv[j].w;
        }
        acc = warpSum(acc);
        if (lane == 0)
            es[l] = (src[b * LL + l] == PAD_ID) ? -1e30f : acc;
    }
    __syncthreads();

    // Phase 2: softmax over L
    float ev = (tid < LL) ? es[tid] : -INFINITY;
    float m  = blockMax(ev, red);
    float p  = (tid < LL) ? __expf(ev - m) : 0.0f;
    float Z  = blockSum(p, red);
    float a  = p / Z;
    if (tid < LL) { es[tid] = a; attn_out[b * LL + tid] = a; }
    __syncthreads();

    // Phase 3: ctx[e] = sum_l attn[l] * enc[b,l,e]  (8 loads in flight)
    float acc = 0.0f;
    const float* eb = enc + (size_t)b * LL * HE + tid;
    for (int l = 0; l < LL; l += 8) {
        float v0 = eb[(size_t)(l + 0) * HE];
        float v1 = eb[(size_t)(l + 1) * HE];
        float v2 = eb[(size_t)(l + 2) * HE];
        float v3 = eb[(size_t)(l + 3) * HE];
        float v4_ = eb[(size_t)(l + 4) * HE];
        float v5 = eb[(size_t)(l + 5) * HE];
        float v6 = eb[(size_t)(l + 6) * HE];
        float v7 = eb[(size_t)(l + 7) * HE];
        acc += es[l + 0] * v0 + es[l + 1] * v1 + es[l + 2] * v2 + es[l + 3] * v3
             + es[l + 4] * v4_ + es[l + 5] * v5 + es[l + 6] * v6 + es[l + 7] * v7;
    }
    ctx_out[b * HE + tid] = acc;

    // Phase 4: p_copy
    float part = s_new[b * HD + tid] * copy_W[tid] + acc * copy_W[HD + tid];
    float tot = blockSum(part, red);
    if (tid == 0) pc_out[b] = sigmoid_fast(tot + copy_b[0]);
}

// ---------------------------------------------------------------------------
// Output: softmax over V, log of [(1-pc)*p_vocab, pc*attn] + 1e-12
// ---------------------------------------------------------------------------
__global__ __launch_bounds__(1024) void output_kernel(
    const float* __restrict__ energy,
    const float* __restrict__ attn,
    const float* __restrict__ pc_in,
    float* __restrict__ out, int t)
{
    __shared__ float red[32];
    int b = blockIdx.x, tid = threadIdx.x;
    const float4* eb4 = (const float4*)(energy + (size_t)b * VV);

    float mx = -INFINITY;
    for (int j = tid; j < VV / 4; j += 1024) {
        float4 v = eb4[j];
        mx = fmaxf(mx, fmaxf(fmaxf(v.x, v.y), fmaxf(v.z, v.w)));
    }
    mx = blockMax(mx, red);

    float sm = 0.0f;
    for (int j = tid; j < VV / 4; j += 1024) {
        float4 v = eb4[j];
        sm += __expf(v.x - mx) + __expf(v.y - mx) + __expf(v.z - mx) + __expf(v.w - mx);
    }
    sm = blockSum(sm, red);

    float pc = pc_in[b];
    float scale = (1.0f - pc) / sm;
    float* ob = out + ((size_t)b * TT + t) * (VV + LL);
    float4* ob4 = (float4*)ob;
    for (int j = tid; j < VV / 4; j += 1024) {
        float4 v = eb4[j], o;
        o.x = __logf(__expf(v.x - mx) * scale + 1e-12f);
        o.y = __logf(__expf(v.y - mx) * scale + 1e-12f);
        o.z = __logf(__expf(v.z - mx) * scale + 1e-12f);
        o.w = __logf(__expf(v.w - mx) * scale + 1e-12f);
        ob4[j] = o;
    }
    const float4* at4 = (const float4*)(attn + (size_t)b * LL);
    float4* oc4 = (float4*)(ob + VV);
    for (int j = tid; j < LL / 4; j += 1024) {
        float4 a = at4[j], o;
        o.x = __logf(fmaf(pc, a.x, 1e-12f));
        o.y = __logf(fmaf(pc, a.y, 1e-12f));
        o.z = __logf(fmaf(pc, a.z, 1e-12f));
        o.w = __logf(fmaf(pc, a.w, 1e-12f));
        oc4[j] = o;
    }
}

// ---------------------------------------------------------------------------
// Host orchestration
// ---------------------------------------------------------------------------
extern "C" void kernel_launch(void* const* d_in, const int* in_sizes, int n_in,
                              void* d_out, int out_size)
{
    const float* enc     = (const float*)d_in[0];
    const float* s_in    = (const float*)d_in[1];
    const int*   src     = (const int*)  d_in[2];
    const int*   tgt     = (const int*)  d_in[3];
    const float* embed   = (const float*)d_in[4];
    const float* W_ih    = (const float*)d_in[5];
    const float* b_ih    = (const float*)d_in[6];
    const float* W_hh    = (const float*)d_in[7];
    const float* b_hh    = (const float*)d_in[8];
    const float* att_Wh  = (const float*)d_in[9];
    const float* att_Ws  = (const float*)d_in[10];
    const float* att_b   = (const float*)d_in[11];
    const float* att_v   = (const float*)d_in[12];
    const float* copy_W  = (const float*)d_in[13];
    const float* copy_b  = (const float*)d_in[14];
    const float* read_W  = (const float*)d_in[15];
    const float* read_b  = (const float*)d_in[16];
    const float* read_Wo = (const float*)d_in[17];
    float* out = (float*)d_out;

    float *p_proj, *p_gi, *p_gh, *p_s0, *p_s1, *p_c0, *p_c1;
    float *p_q, *p_attn, *p_pc, *p_m, *p_energy;
    cudaGetSymbolAddress((void**)&p_proj,   g_enc_proj);
    cudaGetSymbolAddress((void**)&p_gi,     g_gi);
    cudaGetSymbolAddress((void**)&p_gh,     g_gh);
    cudaGetSymbolAddress((void**)&p_s0,     g_s0);
    cudaGetSymbolAddress((void**)&p_s1,     g_s1);
    cudaGetSymbolAddress((void**)&p_c0,     g_c0);
    cudaGetSymbolAddress((void**)&p_c1,     g_c1);
    cudaGetSymbolAddress((void**)&p_q,      g_q);
    cudaGetSymbolAddress((void**)&p_attn,   g_attn);
    cudaGetSymbolAddress((void**)&p_pc,     g_pc);
    cudaGetSymbolAddress((void**)&p_m,      g_m);
    cudaGetSymbolAddress((void**)&p_energy, g_energy);

    cudaMemcpyAsync(p_s0, s_in, BB * HD * sizeof(float),
                    cudaMemcpyDeviceToDevice, 0);
    cudaMemsetAsync(p_c0, 0, BB * HE * sizeof(float), 0);

    // enc_proj = enc_outputs @ att_Wh^T (once)
    {
        GArgs g{};
        g.A = enc; g.lda = HE; g.W = att_Wh;
        g.C = p_proj; g.ldc = AA; g.bias = nullptr;
        g.M = BB * LL; g.N = AA; g.K = HE;
        k_gemm_plain<<<dim3(AA / 64, (BB * LL) / 64), 256, SMEM_GEMM>>>(g);
    }

    float* sbuf[2] = {p_s0, p_s1};
    float* cbuf[2] = {p_c0, p_c1};

    for (int t = 0; t < TT; t++) {
        float* s_cur = sbuf[t & 1];
        float* s_nx  = sbuf[(t + 1) & 1];
        float* c_cur = cbuf[t & 1];
        float* c_nx  = cbuf[(t + 1) & 1];

        // gi = [emb, ctx] @ W_ih^T  and  gh = s @ W_hh^T (fused launch)
        {
            GArgs gi{};
            gi.W = W_ih; gi.C = p_gi; gi.ldc = 3 * HD; gi.bias = nullptr;
            gi.M = BB; gi.N = 3 * HD; gi.K = EE + HE;
            gi.embed = embed; gi.tgt = tgt; gi.t = t; gi.ctx = c_cur;
            GArgs gh{};
            gh.A = s_cur; gh.lda = HD; gh.W = W_hh;
            gh.C = p_gh; gh.ldc = 3 * HD; gh.bias = nullptr;
            gh.M = BB; gh.N = 3 * HD; gh.K = HD;
            k_gates<<<dim3((3 * HD) / 64, BB / 64, 2), 256, SMEM_GEMM>>>(gi, gh);
        }
        gru_kernel<<<(BB * HD) / 256, 256>>>(p_gi, p_gh, b_ih, b_hh, s_cur, s_nx);

        // q = s_new @ att_Ws^T + att_b
        {
            GArgs g{};
            g.A = s_nx; g.lda = HD; g.W = att_Ws;
            g.C = p_q; g.ldc = AA; g.bias = att_b;
            g.M = BB; g.N = AA; g.K = HD;
            k_gemm_plain<<<dim3(AA / 64, BB / 64), 256, SMEM_GEMM>>>(g);
        }

        attn_ctx_kernel<<<BB, 512>>>(p_q, p_proj, enc, att_v, src, s_nx,
                                     copy_W, copy_b, p_attn, c_nx, p_pc);

        // m = maxout([emb, ctx_new, s_new] @ read_W^T + read_b)
        {
            GArgs g{};
            g.W = read_W; g.C = p_m; g.ldc = HD / 2; g.bias = read_b;
            g.M = BB; g.N = HD; g.K = EE + HE + HD;
            g.embed = embed; g.tgt = tgt; g.t = t; g.ctx = c_nx; g.s = s_nx;
            k_gemm_xr_max<<<dim3(HD / 64, BB / 64), 256, SMEM_GEMM>>>(g);
        }
        // energy = m @ read_Wo^T
        {
            GArgs g{};
            g.A = p_m; g.lda = HD / 2; g.W = read_Wo;
            g.C = p_energy; g.ldc = VV; g.bias = nullptr;
            g.M = BB; g.N = VV; g.K = HD / 2;
            k_gemm_plain<<<dim3((VV + 63) / 64, BB / 64), 256, SMEM_GEMM>>>(g);
        }

        output_kernel<<<BB, 1024>>>(p_energy, p_attn, p_pc, out, t);
    }
}

// round 5
// speedup vs baseline: 4.5697x; 1.7587x over previous
#include <cuda_runtime.h>
#include <cuda_fp16.h>
#include <cstdint>
#include <cmath>

// Problem constants
#define BB   128
#define LL   400
#define TT   30
#define EE   300
#define HE   512
#define HD   512
#define AA   512
#define VV   20000
#define PAD_ID 0
#define UNK_ID 1
#define SOS_ID 2

#define STAGES 4
#define SK     40                      // smem row stride in halfs (32 + 8 pad)
#define SMEM_GEMM (2 * STAGES * 64 * SK * 2)   // 40960 bytes

// ---------------------------------------------------------------------------
// Scratch (device globals; distinct symbols only, all 256B aligned)
// ---------------------------------------------------------------------------
__device__ __align__(256) __half g_enc_h [(size_t)BB * LL * HE];     // 52 MB
__device__ __align__(256) __half g_proj_h[(size_t)BB * LL * AA];     // 52 MB
__device__ __align__(256) __half g_embed_h[(size_t)VV * 304];        // 12 MB
__device__ __align__(256) __half g_Wih_e[1536 * 304];
__device__ __align__(256) __half g_Wih_c[1536 * 512];
__device__ __align__(256) __half g_Whh  [1536 * 512];
__device__ __align__(256) __half g_Ws   [512 * 512];
__device__ __align__(256) __half g_Wh   [512 * 512];
__device__ __align__(256) __half g_Wr_e [512 * 304];
__device__ __align__(256) __half g_Wr_c [512 * 1024];
__device__ __align__(256) __half g_Wo   [(size_t)VV * 256];
__device__ __align__(256) float  g_giemb[(size_t)TT * BB * 1536];    // 23.6 MB
__device__ __align__(256) float  g_rvemb[(size_t)TT * BB * 512];     // 7.9 MB
__device__ __align__(256) float  g_gi_p [4 * BB * 1536];
__device__ __align__(256) float  g_gh_p [4 * BB * 1536];
__device__ __align__(256) float  g_q_p  [4 * BB * 512];
__device__ __align__(256) float  g_rv_p [4 * BB * 512];
__device__ __align__(256) float  g_s0f  [BB * HD];
__device__ __align__(256) float  g_s1f  [BB * HD];
__device__ __align__(256) __half g_sh0  [BB * HD];
__device__ __align__(256) __half g_sh1  [BB * HD];
__device__ __align__(256) __half g_ch0  [BB * HE];
__device__ __align__(256) __half g_ch1  [BB * HE];
__device__ __align__(256) __half g_mh   [BB * 256];
__device__ __align__(256) float  g_attn [BB * LL];
__device__ __align__(256) float  g_pc   [BB];
__device__ __align__(256) float  g_energy[(size_t)BB * VV];          // 10.2 MB

// ---------------------------------------------------------------------------
// Low-level helpers
// ---------------------------------------------------------------------------
__device__ __forceinline__ void cp_async16(uint32_t dst, const void* src, int bytes) {
    asm volatile("cp.async.ca.shared.global [%0], [%1], 16, %2;\n"
                 :: "r"(dst), "l"(src), "r"(bytes));
}
__device__ __forceinline__ void cp_commit() {
    asm volatile("cp.async.commit_group;\n" ::: "memory");
}
template <int N>
__device__ __forceinline__ void cp_wait() {
    asm volatile("cp.async.wait_group %0;\n" :: "n"(N) : "memory");
}

__device__ __forceinline__ void ldsm4(uint32_t (&r)[4], uint32_t addr) {
    asm volatile("ldmatrix.sync.aligned.m8n8.x4.shared.b16 {%0,%1,%2,%3}, [%4];"
                 : "=r"(r[0]), "=r"(r[1]), "=r"(r[2]), "=r"(r[3]) : "r"(addr));
}

__device__ __forceinline__ void mma_f16(float (&c)[4], const uint32_t (&a)[4],
                                        uint32_t b0, uint32_t b1) {
    asm volatile(
        "mma.sync.aligned.m16n8k16.row.col.f32.f16.f16.f32 "
        "{%0,%1,%2,%3}, {%4,%5,%6,%7}, {%8,%9}, {%0,%1,%2,%3};\n"
        : "+f"(c[0]), "+f"(c[1]), "+f"(c[2]), "+f"(c[3])
        : "r"(a[0]), "r"(a[1]), "r"(a[2]), "r"(a[3]), "r"(b0), "r"(b1));
}

__device__ __forceinline__ float tanhA(float x) {
    float y;
    asm("tanh.approx.f32 %0, %1;" : "=f"(y) : "f"(x));
    return y;
}
__device__ __forceinline__ float sigmoid_fast(float x) {
    return __fdividef(1.0f, 1.0f + __expf(-x));
}
__device__ __forceinline__ float tanh_fast(float x) {
    x = fminf(15.0f, fmaxf(-15.0f, x));
    float e = __expf(2.0f * x);
    return 1.0f - __fdividef(2.0f, e + 1.0f);
}

__device__ __forceinline__ float warpMax(float v) {
    #pragma unroll
    for (int o = 16; o; o >>= 1) v = fmaxf(v, __shfl_xor_sync(0xffffffffu, v, o));
    return v;
}
__device__ __forceinline__ float warpSum(float v) {
    #pragma unroll
    for (int o = 16; o; o >>= 1) v += __shfl_xor_sync(0xffffffffu, v, o);
    return v;
}
__device__ __forceinline__ float blockMax(float v, float* red) {
    v = warpMax(v);
    int w = threadIdx.x >> 5, l = threadIdx.x & 31, nw = blockDim.x >> 5;
    if (l == 0) red[w] = v;
    __syncthreads();
    if (threadIdx.x < 32) {
        float x = (threadIdx.x < nw) ? red[threadIdx.x] : -INFINITY;
        x = warpMax(x);
        if (threadIdx.x == 0) red[0] = x;
    }
    __syncthreads();
    v = red[0];
    __syncthreads();
    return v;
}
__device__ __forceinline__ float blockSum(float v, float* red) {
    v = warpSum(v);
    int w = threadIdx.x >> 5, l = threadIdx.x & 31, nw = blockDim.x >> 5;
    if (l == 0) red[w] = v;
    __syncthreads();
    if (threadIdx.x < 32) {
        float x = (threadIdx.x < nw) ? red[threadIdx.x] : 0.0f;
        x = warpSum(x);
        if (threadIdx.x == 0) red[0] = x;
    }
    __syncthreads();
    v = red[0];
    __syncthreads();
    return v;
}

// ---------------------------------------------------------------------------
// Convert/repack fp32 -> fp16 with optional column slice + zero padding
// ---------------------------------------------------------------------------
__global__ void cvt_pad(const float* __restrict__ src, __half* __restrict__ dst,
                        int rows, int sstr, int soff, int dstr, int clen)
{
    int total = rows * dstr;
    for (int i = blockIdx.x * blockDim.x + threadIdx.x; i < total;
         i += gridDim.x * blockDim.x) {
        int r = i / dstr, c = i - r * dstr;
        float v = (c < clen) ? src[(size_t)r * sstr + soff + c] : 0.0f;
        dst[i] = __float2half(v);
    }
}

// ---------------------------------------------------------------------------
// fp16 tensor-core GEMM: C[M,N] = A[M,K] @ W[N,K]^T
// block tile 64x64, K-chunk 32, 128 threads (4 warps, 2x2, warp tile 32x32)
// ---------------------------------------------------------------------------
struct GH {
    const __half* A; int lda;       // MODE_PLAIN
    const __half* W; int ldw;
    float* C; int ldc;
    int N;
    int K;                          // K per split (multiple of 32)
    int kbeg, kend;                 // absolute column range [kbeg, kend)
    const __half* embed;            // MODE_EMB
    const int*    tgt;
    const __half* ctx;              // MODE_CS
    const __half* s;
};

#define MODE_PLAIN 0
#define MODE_EMB   1   // A row m -> embed_h[word(t=m>>7, b=m&127)]
#define MODE_CS    2   // A = [ctx(512) | s(512)]

template <int MODE, bool OUTH>
__device__ __forceinline__ void grun(const GH& g) {
    extern __shared__ __half smh[];
    __half* As = smh;
    __half* Ws = smh + STAGES * 64 * SK;

    const int tid = threadIdx.x, lane = tid & 31, warp = tid >> 5;
    const int wm = warp >> 1, wn = warp & 1;
    const int mt0 = blockIdx.y * 64, nt0 = blockIdx.x * 64;

    const int r0 = tid >> 2, kc = (tid & 3) * 8;
    const int r1 = r0 + 32;
    const int gm0 = mt0 + r0, gm1 = mt0 + r1;
    const int gn0 = nt0 + r0, gn1 = nt0 + r1;

    const __half *a0 = nullptr, *a1 = nullptr;
    const __half *c0p = nullptr, *c1p = nullptr, *s0p = nullptr, *s1p = nullptr;
    if (MODE == MODE_PLAIN) {
        a0 = g.A + (size_t)gm0 * g.lda;
        a1 = g.A + (size_t)gm1 * g.lda;
    } else if (MODE == MODE_EMB) {
        int t0 = gm0 >> 7, b0 = gm0 & 127;
        int w0 = (t0 == 0) ? SOS_ID : g.tgt[b0 * TT + t0 - 1];
        if (w0 >= VV) w0 = UNK_ID;
        int t1 = gm1 >> 7, b1 = gm1 & 127;
        int w1 = (t1 == 0) ? SOS_ID : g.tgt[b1 * TT + t1 - 1];
        if (w1 >= VV) w1 = UNK_ID;
        a0 = g.embed + (size_t)w0 * 304;
        a1 = g.embed + (size_t)w1 * 304;
    } else {
        c0p = g.ctx + gm0 * 512; c1p = g.ctx + gm1 * 512;
        s0p = g.s   + gm0 * 512; s1p = g.s   + gm1 * 512;
    }
    const bool n0ok = (gn0 < g.N), n1ok = (gn1 < g.N);
    const __half* w0p = g.W + (size_t)(n0ok ? gn0 : 0) * g.ldw;
    const __half* w1p = g.W + (size_t)(n1ok ? gn1 : 0) * g.ldw;

    const uint32_t asB = (uint32_t)__cvta_generic_to_shared(As);
    const uint32_t wsB = (uint32_t)__cvta_generic_to_shared(Ws);
    const int STB = 64 * SK * 2;
    const uint32_t aD0 = asB + (r0 * SK + kc) * 2;
    const uint32_t aD1 = asB + (r1 * SK + kc) * 2;
    const uint32_t wD0 = wsB + (r0 * SK + kc) * 2;
    const uint32_t wD1 = wsB + (r1 * SK + kc) * 2;

    const int nk = (g.kend - g.kbeg + 31) >> 5;

    auto pf = [&](int i) {
        int kg = g.kbeg + i * 32 + kc;
        int buf = (i & 3) * STB;
        bool v = kg < g.kend;
        const __half *sa0, *sa1;
        if (MODE == MODE_CS) {
            sa0 = (kg < 512) ? c0p + kg : s0p + (kg - 512);
            sa1 = (kg < 512) ? c1p + kg : s1p + (kg - 512);
        } else {
            sa0 = a0 + kg; sa1 = a1 + kg;
        }
        if (!v) { sa0 = g.W; sa1 = g.W; }
        cp_async16(aD0 + buf, sa0, v ? 16 : 0);
        cp_async16(aD1 + buf, sa1, v ? 16 : 0);
        bool v0 = v && n0ok, v1 = v && n1ok;
        cp_async16(wD0 + buf, v0 ? (w0p + kg) : g.W, v0 ? 16 : 0);
        cp_async16(wD1 + buf, v1 ? (w1p + kg) : g.W, v1 ? 16 : 0);
    };

    #pragma unroll
    for (int p = 0; p < 3; p++) {
        if (p < nk) pf(p);
        cp_commit();
    }

    float c[2][4][4] = {};
    const int lr = lane & 15, lk = (lane >> 4) * 8;

    for (int i = 0; i < nk; i++) {
        if (i + 3 < nk) pf(i + 3);
        cp_commit();
        cp_wait<3>();
        __syncthreads();

        const uint32_t ab = asB + (i & 3) * STB;
        const uint32_t wb = wsB + (i & 3) * STB;

        #pragma unroll
        for (int kk = 0; kk < 32; kk += 16) {
            uint32_t a[2][4], bb[2][4];
            #pragma unroll
            for (int mt = 0; mt < 2; mt++)
                ldsm4(a[mt], ab + ((wm * 32 + mt * 16 + lr) * SK + kk + lk) * 2);
            #pragma unroll
            for (int n2 = 0; n2 < 2; n2++)
                ldsm4(bb[n2], wb + ((wn * 32 + n2 * 16 + lr) * SK + kk + lk) * 2);
            #pragma unroll
            for (int mt = 0; mt < 2; mt++)
                #pragma unroll
                for (int ns = 0; ns < 4; ns++) {
                    int n2 = ns >> 1, sel = ns & 1;
                    mma_f16(c[mt][ns], a[mt], bb[n2][sel], bb[n2][sel + 2]);
                }
        }
        __syncthreads();
    }

    // Epilogue
    const int gr = lane >> 2, gc = (lane & 3) * 2;
    #pragma unroll
    for (int mt = 0; mt < 2; mt++)
        #pragma unroll
        for (int ns = 0; ns < 4; ns++) {
            int row = mt0 + wm * 32 + mt * 16 + gr;
            int col = nt0 + wn * 32 + ns * 8 + gc;
            if (col < g.N) {
                if (OUTH) {
                    __half* Ch = (__half*)g.C;
                    Ch[(size_t)row * g.ldc + col]           = __float2half(c[mt][ns][0]);
                    Ch[(size_t)row * g.ldc + col + 1]       = __float2half(c[mt][ns][1]);
                    Ch[(size_t)(row + 8) * g.ldc + col]     = __float2half(c[mt][ns][2]);
                    Ch[(size_t)(row + 8) * g.ldc + col + 1] = __float2half(c[mt][ns][3]);
                } else {
                    g.C[(size_t)row * g.ldc + col]           = c[mt][ns][0];
                    g.C[(size_t)row * g.ldc + col + 1]       = c[mt][ns][1];
                    g.C[(size_t)(row + 8) * g.ldc + col]     = c[mt][ns][2];
                    g.C[(size_t)(row + 8) * g.ldc + col + 1] = c[mt][ns][3];
                }
            }
        }
}

__global__ __launch_bounds__(128) void k_g_plain(GH g)   { grun<MODE_PLAIN, false>(g); }
__global__ __launch_bounds__(128) void k_g_plain_h(GH g) { grun<MODE_PLAIN, true >(g); }
__global__ __launch_bounds__(128) void k_g_emb(GH g)     { grun<MODE_EMB,   false>(g); }
__global__ __launch_bounds__(128) void k_g_plain_split(GH g) {
    int sp = blockIdx.z;
    g.kbeg = sp * g.K; g.kend = g.kbeg + g.K;
    g.C += (size_t)sp * BB * g.ldc;
    grun<MODE_PLAIN, false>(g);
}
__global__ __launch_bounds__(128) void k_g_cs_split(GH g) {
    int sp = blockIdx.z;
    g.kbeg = sp * g.K; g.kend = g.kbeg + g.K;
    g.C += (size_t)sp * BB * g.ldc;
    grun<MODE_CS, false>(g);
}
__global__ __launch_bounds__(128) void k_gates(GH gi, GH gh) {
    int z = blockIdx.z;
    GH g = (z < 4) ? gi : gh;
    int sp = z & 3;
    g.kbeg = sp * g.K; g.kend = g.kbeg + g.K;
    g.C += (size_t)sp * BB * g.ldc;
    grun<MODE_PLAIN, false>(g);
}

// ---------------------------------------------------------------------------
// GRU: reduce split-K partials + precomputed emb part, then gate math
// ---------------------------------------------------------------------------
__global__ __launch_bounds__(256) void gru_kernel(
    const float* __restrict__ gip, const float* __restrict__ ghp,
    const float* __restrict__ giemb,
    const float* __restrict__ b_ih, const float* __restrict__ b_hh,
    const float* __restrict__ s_old,
    float* __restrict__ s_new, __half* __restrict__ s_h, int t)
{
    int idx = blockIdx.x * blockDim.x + threadIdx.x;   // BB*HD
    int b = idx >> 9, h = idx & 511;
    size_t ob = (size_t)b * 1536;
    size_t oe = ((size_t)t * BB + b) * 1536;

    float ir = giemb[oe + h]            + b_ih[h];
    float iz = giemb[oe + HD + h]       + b_ih[HD + h];
    float in = giemb[oe + 2 * HD + h]   + b_ih[2 * HD + h];
    float hr = b_hh[h], hz = b_hh[HD + h], hn = b_hh[2 * HD + h];
    #pragma unroll
    for (int z = 0; z < 4; z++) {
        size_t o = (size_t)z * BB * 1536 + ob;
        ir += gip[o + h];      iz += gip[o + HD + h];  in += gip[o + 2 * HD + h];
        hr += ghp[o + h];      hz += ghp[o + HD + h];  hn += ghp[o + 2 * HD + h];
    }
    float r = sigmoid_fast(ir + hr);
    float z = sigmoid_fast(iz + hz);
    float n = tanh_fast(in + r * hn);
    float so = s_old[idx];
    float sn = (1.0f - z) * n + z * so;
    s_new[idx] = sn;
    s_h[idx] = __float2half(sn);
}

// ---------------------------------------------------------------------------
// Fused attention (fp16 tables): q-reduce -> e -> softmax -> ctx -> p_copy
// ---------------------------------------------------------------------------
__global__ __launch_bounds__(512) void attn_kernel(
    const float* __restrict__ qp,      // [4][B][512] partials
    const float* __restrict__ att_b,
    const __half* __restrict__ proj,   // [B,L,A] fp16
    const __half* __restrict__ ench,   // [B,L,HE] fp16
    const float* __restrict__ vvec,
    const int*   __restrict__ src,
    const float* __restrict__ s_new,
    const float* __restrict__ copy_W,
    const float* __restrict__ copy_b,
    float* __restrict__ attn_out,
    __half* __restrict__ ctx_h,
    float* __restrict__ pc_out)
{
    __shared__ __align__(16) float es[LL];
    __shared__ float part[2][HE];
    __shared__ float red[32];

    int b = blockIdx.x, tid = threadIdx.x;
    int warp = tid >> 5, lane = tid & 31;

    float qf[2][8], vf[2][8];
    #pragma unroll
    for (int j = 0; j < 2; j++) {
        int base = (lane + 32 * j) * 8;
        float4 b0 = *(const float4*)(att_b + base);
        float4 b1 = *(const float4*)(att_b + base + 4);
        qf[j][0] = b0.x; qf[j][1] = b0.y; qf[j][2] = b0.z; qf[j][3] = b0.w;
        qf[j][4] = b1.x; qf[j][5] = b1.y; qf[j][6] = b1.z; qf[j][7] = b1.w;
        #pragma unroll
        for (int z = 0; z < 4; z++) {
            const float* qz = qp + ((size_t)z * BB + b) * 512 + base;
            float4 q0 = *(const float4*)qz;
            float4 q1 = *(const float4*)(qz + 4);
            qf[j][0] += q0.x; qf[j][1] += q0.y; qf[j][2] += q0.z; qf[j][3] += q0.w;
            qf[j][4] += q1.x; qf[j][5] += q1.y; qf[j][6] += q1.z; qf[j][7] += q1.w;
        }
        float4 v0 = *(const float4*)(vvec + base);
        float4 v1 = *(const float4*)(vvec + base + 4);
        vf[j][0] = v0.x; vf[j][1] = v0.y; vf[j][2] = v0.z; vf[j][3] = v0.w;
        vf[j][4] = v1.x; vf[j][5] = v1.y; vf[j][6] = v1.z; vf[j][7] = v1.w;
    }

    // Phase 1: scores
    for (int l = warp; l < LL; l += 16) {
        const uint4* pp = (const uint4*)(proj + ((size_t)b * LL + l) * AA);
        float acc = 0.0f;
        #pragma unroll
        for (int j = 0; j < 2; j++) {
            uint4 pv = pp[lane + 32 * j];
            const __half2* h2 = (const __half2*)&pv;
            #pragma unroll
            for (int p = 0; p < 4; p++) {
                float2 f = __half22float2(h2[p]);
                acc += tanhA(f.x + qf[j][2 * p])     * vf[j][2 * p];
                acc += tanhA(f.y + qf[j][2 * p + 1]) * vf[j][2 * p + 1];
            }
        }
        acc = warpSum(acc);
        if (lane == 0)
            es[l] = (src[b * LL + l] == PAD_ID) ? -1e30f : acc;
    }
    __syncthreads();

    // Phase 2: softmax over L
    float ev = (tid < LL) ? es[tid] : -INFINITY;
    float m  = blockMax(ev, red);
    float p  = (tid < LL) ? __expf(ev - m) : 0.0f;
    float Z  = blockSum(p, red);
    float a  = p / Z;
    if (tid < LL) { es[tid] = a; attn_out[b * LL + tid] = a; }
    __syncthreads();

    // Phase 3: ctx via fp16 enc, 2 L-groups x 256 column-pairs
    int gg = tid >> 8, cc = tid & 255;
    const __half2* eb = (const __half2*)(ench + (size_t)b * LL * HE) + cc;
    float ax = 0.0f, ay = 0.0f;
    int l0 = gg * 200;
    #pragma unroll 4
    for (int l = l0; l < l0 + 200; l++) {
        float2 f = __half22float2(eb[(size_t)l * 256]);
        ax += es[l] * f.x;
        ay += es[l] * f.y;
    }
    part[gg][2 * cc]     = ax;
    part[gg][2 * cc + 1] = ay;
    __syncthreads();

    float ctxv = part[0][tid] + part[1][tid];
    ctx_h[b * HE + tid] = __float2half(ctxv);

    // Phase 4: p_copy
    float pp_ = s_new[b * HD + tid] * copy_W[tid] + ctxv * copy_W[HD + tid];
    float tot = blockSum(pp_, red);
    if (tid == 0) pc_out[b] = sigmoid_fast(tot + copy_b[0]);
}

// ---------------------------------------------------------------------------
// Maxout reduce: m = maxout(sum rv partials + rvemb + bias) -> fp16
// ---------------------------------------------------------------------------
__global__ __launch_bounds__(256) void mred_kernel(
    const float* __restrict__ rvp, const float* __restrict__ rvemb,
    const float* __restrict__ read_b, __half* __restrict__ mh, int t)
{
    int idx = blockIdx.x * blockDim.x + threadIdx.x;   // BB*256
    int b = idx >> 8, c = idx & 255;
    int h0 = 2 * c, h1 = 2 * c + 1;
    size_t oe = ((size_t)t * BB + b) * 512;
    float r0 = rvemb[oe + h0] + read_b[h0];
    float r1 = rvemb[oe + h1] + read_b[h1];
    #pragma unroll
    for (int z = 0; z < 4; z++) {
        size_t o = (size_t)z * BB * 512 + (size_t)b * 512;
        r0 += rvp[o + h0];
        r1 += rvp[o + h1];
    }
    mh[idx] = __float2half(fmaxf(r0, r1));
}

// ---------------------------------------------------------------------------
// Output: softmax over V, log of [(1-pc)*p_vocab, pc*attn] + 1e-12
// ---------------------------------------------------------------------------
__global__ __launch_bounds__(1024) void output_kernel(
    const float* __restrict__ energy,
    const float* __restrict__ attn,
    const float* __restrict__ pc_in,
    float* __restrict__ out, int t)
{
    __shared__ float red[32];
    int b = blockIdx.x, tid = threadIdx.x;
    const float4* eb4 = (const float4*)(energy + (size_t)b * VV);

    float mx = -INFINITY;
    for (int j = tid; j < VV / 4; j += 1024) {
        float4 v = eb4[j];
        mx = fmaxf(mx, fmaxf(fmaxf(v.x, v.y), fmaxf(v.z, v.w)));
    }
    mx = blockMax(mx, red);

    float sm = 0.0f;
    for (int j = tid; j < VV / 4; j += 1024) {
        float4 v = eb4[j];
        sm += __expf(v.x - mx) + __expf(v.y - mx) + __expf(v.z - mx) + __expf(v.w - mx);
    }
    sm = blockSum(sm, red);

    float pc = pc_in[b];
    float scale = (1.0f - pc) / sm;
    float* ob = out + ((size_t)b * TT + t) * (VV + LL);
    float4* ob4 = (float4*)ob;
    for (int j = tid; j < VV / 4; j += 1024) {
        float4 v = eb4[j], o;
        o.x = __logf(__expf(v.x - mx) * scale + 1e-12f);
        o.y = __logf(__expf(v.y - mx) * scale + 1e-12f);
        o.z = __logf(__expf(v.z - mx) * scale + 1e-12f);
        o.w = __logf(__expf(v.w - mx) * scale + 1e-12f);
        ob4[j] = o;
    }
    const float4* at4 = (const float4*)(attn + (size_t)b * LL);
    float4* oc4 = (float4*)(ob + VV);
    for (int j = tid; j < LL / 4; j += 1024) {
        float4 a = at4[j], o;
        o.x = __logf(fmaf(pc, a.x, 1e-12f));
        o.y = __logf(fmaf(pc, a.y, 1e-12f));
        o.z = __logf(fmaf(pc, a.z, 1e-12f));
        o.w = __logf(fmaf(pc, a.w, 1e-12f));
        oc4[j] = o;
    }
}

// ---------------------------------------------------------------------------
// Host orchestration
// ---------------------------------------------------------------------------
static inline void cvt(const float* s, __half* d, int rows, int sstr, int soff,
                       int dstr, int clen) {
    int total = rows * dstr;
    int grid = (total + 255) / 256;
    if (grid > 8192) grid = 8192;
    cvt_pad<<<grid, 256>>>(s, d, rows, sstr, soff, dstr, clen);
}

extern "C" void kernel_launch(void* const* d_in, const int* in_sizes, int n_in,
                              void* d_out, int out_size)
{
    const float* enc     = (const float*)d_in[0];
    const float* s_in    = (const float*)d_in[1];
    const int*   src     = (const int*)  d_in[2];
    const int*   tgt     = (const int*)  d_in[3];
    const float* embed   = (const float*)d_in[4];
    const float* W_ih    = (const float*)d_in[5];
    const float* b_ih    = (const float*)d_in[6];
    const float* W_hh    = (const float*)d_in[7];
    const float* b_hh    = (const float*)d_in[8];
    const float* att_Wh  = (const float*)d_in[9];
    const float* att_Ws  = (const float*)d_in[10];
    const float* att_b   = (const float*)d_in[11];
    const float* att_v   = (const float*)d_in[12];
    const float* copy_W  = (const float*)d_in[13];
    const float* copy_b  = (const float*)d_in[14];
    const float* read_W  = (const float*)d_in[15];
    const float* read_b  = (const float*)d_in[16];
    const float* read_Wo = (const float*)d_in[17];
    float* out = (float*)d_out;

    __half *p_ench, *p_projh, *p_embh, *p_Wihe, *p_Wihc, *p_Whh, *p_Ws, *p_Wh;
    __half *p_Wre, *p_Wrc, *p_Wo, *p_sh0, *p_sh1, *p_ch0, *p_ch1, *p_mh;
    float *p_giemb, *p_rvemb, *p_gip, *p_ghp, *p_qp, *p_rvp;
    float *p_s0, *p_s1, *p_attn, *p_pc, *p_energy;

    cudaGetSymbolAddress((void**)&p_ench,  g_enc_h);
    cudaGetSymbolAddress((void**)&p_projh, g_proj_h);
    cudaGetSymbolAddress((void**)&p_embh,  g_embed_h);
    cudaGetSymbolAddress((void**)&p_Wihe,  g_Wih_e);
    cudaGetSymbolAddress((void**)&p_Wihc,  g_Wih_c);
    cudaGetSymbolAddress((void**)&p_Whh,   g_Whh);
    cudaGetSymbolAddress((void**)&p_Ws,    g_Ws);
    cudaGetSymbolAddress((void**)&p_Wh,    g_Wh);
    cudaGetSymbolAddress((void**)&p_Wre,   g_Wr_e);
    cudaGetSymbolAddress((void**)&p_Wrc,   g_Wr_c);
    cudaGetSymbolAddress((void**)&p_Wo,    g_Wo);
    cudaGetSymbolAddress((void**)&p_giemb, g_giemb);
    cudaGetSymbolAddress((void**)&p_rvemb, g_rvemb);
    cudaGetSymbolAddress((void**)&p_gip,   g_gi_p);
    cudaGetSymbolAddress((void**)&p_ghp,   g_gh_p);
    cudaGetSymbolAddress((void**)&p_qp,    g_q_p);
    cudaGetSymbolAddress((void**)&p_rvp,   g_rv_p);
    cudaGetSymbolAddress((void**)&p_s0,    g_s0f);
    cudaGetSymbolAddress((void**)&p_s1,    g_s1f);
    cudaGetSymbolAddress((void**)&p_sh0,   g_sh0);
    cudaGetSymbolAddress((void**)&p_sh1,   g_sh1);
    cudaGetSymbolAddress((void**)&p_ch0,   g_ch0);
    cudaGetSymbolAddress((void**)&p_ch1,   g_ch1);
    cudaGetSymbolAddress((void**)&p_mh,    g_mh);
    cudaGetSymbolAddress((void**)&p_attn,  g_attn);
    cudaGetSymbolAddress((void**)&p_pc,    g_pc);
    cudaGetSymbolAddress((void**)&p_energy,g_energy);

    // ---- Precompute: conversions / repacks ----
    cvt(enc,     p_ench, BB * LL, HE, 0, HE, HE);
    cvt(embed,   p_embh, VV, EE, 0, 304, EE);
    cvt(W_ih,    p_Wihe, 1536, 812, 0, 304, 300);
    cvt(W_ih,    p_Wihc, 1536, 812, 300, 512, 512);
    cvt(W_hh,    p_Whh,  1536, 512, 0, 512, 512);
    cvt(att_Ws,  p_Ws,   512, 512, 0, 512, 512);
    cvt(att_Wh,  p_Wh,   512, 512, 0, 512, 512);
    cvt(read_W,  p_Wre,  512, 1324, 0, 304, 300);
    cvt(read_W,  p_Wrc,  512, 1324, 300, 1024, 1024);
    cvt(read_Wo, p_Wo,   VV, 256, 0, 256, 256);
    cvt(s_in,    p_sh0,  BB, HD, 0, HD, HD);

    cudaMemcpyAsync(p_s0, s_in, BB * HD * sizeof(float),
                    cudaMemcpyDeviceToDevice, 0);
    cudaMemsetAsync(p_ch0, 0, BB * HE * sizeof(__half), 0);

    // ---- Precompute: big GEMMs ----
    {   // proj = enc @ att_Wh^T -> fp16
        GH g{}; g.A = p_ench; g.lda = HE; g.W = p_Wh; g.ldw = 512;
        g.C = (float*)p_projh; g.ldc = AA; g.N = AA;
        g.kbeg = 0; g.kend = 512;
        k_g_plain_h<<<dim3(8, 800), 128, SMEM_GEMM>>>(g);
    }
    {   // giemb[all t] = emb @ Wih_e^T
        GH g{}; g.embed = p_embh; g.tgt = tgt; g.W = p_Wihe; g.ldw = 304;
        g.C = p_giemb; g.ldc = 1536; g.N = 1536;
        g.kbeg = 0; g.kend = 304;
        k_g_emb<<<dim3(24, 60), 128, SMEM_GEMM>>>(g);
    }
    {   // rvemb[all t] = emb @ Wr_e^T
        GH g{}; g.embed = p_embh; g.tgt = tgt; g.W = p_Wre; g.ldw = 304;
        g.C = p_rvemb; g.ldc = 512; g.N = 512;
        g.kbeg = 0; g.kend = 304;
        k_g_emb<<<dim3(8, 60), 128, SMEM_GEMM>>>(g);
    }

    __half* shb[2] = {p_sh0, p_sh1};
    __half* chb[2] = {p_ch0, p_ch1};
    float*  sb[2]  = {p_s0, p_s1};

    for (int t = 0; t < TT; t++) {
        int cu = t & 1, nx = (t + 1) & 1;

        {   // gi_ctx (splitK4) + gh (splitK4), fused launch
            GH gi{}; gi.A = chb[cu]; gi.lda = 512; gi.W = p_Wihc; gi.ldw = 512;
            gi.C = p_gip; gi.ldc = 1536; gi.N = 1536; gi.K = 128;
            GH gh{}; gh.A = shb[cu]; gh.lda = 512; gh.W = p_Whh; gh.ldw = 512;
            gh.C = p_ghp; gh.ldc = 1536; gh.N = 1536; gh.K = 128;
            k_gates<<<dim3(24, 2, 8), 128, SMEM_GEMM>>>(gi, gh);
        }
        gru_kernel<<<(BB * HD) / 256, 256>>>(p_gip, p_ghp, p_giemb,
                                             b_ih, b_hh, sb[cu], sb[nx],
                                             shb[nx], t);
        {   // q partials = s_new @ att_Ws^T (splitK4)
            GH g{}; g.A = shb[nx]; g.lda = 512; g.W = p_Ws; g.ldw = 512;
            g.C = p_qp; g.ldc = 512; g.N = 512; g.K = 128;
            k_g_plain_split<<<dim3(8, 2, 4), 128, SMEM_GEMM>>>(g);
        }
        attn_kernel<<<BB, 512>>>(p_qp, att_b, p_projh, p_ench, att_v, src,
                                 sb[nx], copy_W, copy_b,
                                 p_attn, chb[nx], p_pc);
        {   // rvec partials = [ctx_new, s_new] @ Wr_c^T (splitK4)
            GH g{}; g.ctx = chb[nx]; g.s = shb[nx]; g.W = p_Wrc; g.ldw = 1024;
            g.C = p_rvp; g.ldc = 512; g.N = 512; g.K = 256;
            k_g_cs_split<<<dim3(8, 2, 4), 128, SMEM_GEMM>>>(g);
        }
        mred_kernel<<<BB, 256>>>(p_rvp, p_rvemb, read_b, p_mh, t);
        {   // energy = m @ read_Wo^T
            GH g{}; g.A = p_mh; g.lda = 256; g.W = p_Wo; g.ldw = 256;
            g.C = p_energy; g.ldc = VV; g.N = VV;
            g.kbeg = 0; g.kend = 256;
            k_g_plain<<<dim3(313, 2), 128, SMEM_GEMM>>>(g);
        }
        output_kernel<<<BB, 1024>>>(p_energy, p_attn, p_pc, out, t);
    }
}

// round 6
// speedup vs baseline: 5.4118x; 1.1843x over previous
#include <cuda_runtime.h>
#include <cuda_fp16.h>
#include <cstdint>
#include <cmath>

// Problem constants
#define BB   128
#define LL   400
#define TT   30
#define EE   300
#define HE   512
#define HD   512
#define AA   512
#define VV   20000
#define PAD_ID 0
#define UNK_ID 1
#define SOS_ID 2

#define STAGES 4
#define SK     40                      // smem row stride in halfs (32 + 8 pad)
#define SMEM_GEMM (2 * STAGES * 64 * SK * 2)   // 40960 bytes

// ---------------------------------------------------------------------------
// Scratch (device globals; distinct symbols only, all 256B aligned)
// ---------------------------------------------------------------------------
__device__ __align__(256) __half g_enc_h [(size_t)BB * LL * HE];     // 52 MB
__device__ __align__(256) __half g_proj_h[(size_t)BB * LL * AA];     // 52 MB
__device__ __align__(256) __half g_embed_h[(size_t)VV * 304];        // 12 MB
__device__ __align__(256) __half g_Wih_e[1536 * 304];
__device__ __align__(256) __half g_Wih_c[1536 * 512];
__device__ __align__(256) __half g_Whh  [1536 * 512];
__device__ __align__(256) __half g_Ws   [512 * 512];
__device__ __align__(256) __half g_Wh   [512 * 512];
__device__ __align__(256) __half g_Wr_e [512 * 304];
__device__ __align__(256) __half g_Wr_c [512 * 1024];
__device__ __align__(256) __half g_Wo   [(size_t)VV * 256];
__device__ __align__(256) float  g_giemb[(size_t)TT * BB * 1536];    // 23.6 MB
__device__ __align__(256) float  g_rvemb[(size_t)TT * BB * 512];     // 7.9 MB
__device__ __align__(256) float  g_gi_p [4 * BB * 1536];
__device__ __align__(256) float  g_gh_p [4 * BB * 1536];
__device__ __align__(256) float  g_q_p  [4 * BB * 512];
__device__ __align__(256) float  g_rv_p [4 * BB * 512];
// Per-step ring buffers (no cross-stream reuse hazards)
__device__ __align__(256) float  g_sf  [(size_t)(TT + 1) * BB * HD]; // 8.1 MB
__device__ __align__(256) __half g_shh [(size_t)(TT + 1) * BB * HD]; // 4.1 MB
__device__ __align__(256) __half g_chh [(size_t)(TT + 1) * BB * HE]; // 4.1 MB
__device__ __align__(256) float  g_attnb[(size_t)TT * BB * LL];      // 6.1 MB
__device__ __align__(256) float  g_pcb  [TT * BB];
__device__ __align__(256) __half g_mh   [BB * 256];
__device__ __align__(256) float  g_energy[(size_t)BB * VV];          // 10.2 MB

// ---------------------------------------------------------------------------
// Low-level helpers
// ---------------------------------------------------------------------------
__device__ __forceinline__ void cp_async16(uint32_t dst, const void* src, int bytes) {
    asm volatile("cp.async.ca.shared.global [%0], [%1], 16, %2;\n"
                 :: "r"(dst), "l"(src), "r"(bytes));
}
__device__ __forceinline__ void cp_commit() {
    asm volatile("cp.async.commit_group;\n" ::: "memory");
}
template <int N>
__device__ __forceinline__ void cp_wait() {
    asm volatile("cp.async.wait_group %0;\n" :: "n"(N) : "memory");
}

__device__ __forceinline__ void ldsm4(uint32_t (&r)[4], uint32_t addr) {
    asm volatile("ldmatrix.sync.aligned.m8n8.x4.shared.b16 {%0,%1,%2,%3}, [%4];"
                 : "=r"(r[0]), "=r"(r[1]), "=r"(r[2]), "=r"(r[3]) : "r"(addr));
}

__device__ __forceinline__ void mma_f16(float (&c)[4], const uint32_t (&a)[4],
                                        uint32_t b0, uint32_t b1) {
    asm volatile(
        "mma.sync.aligned.m16n8k16.row.col.f32.f16.f16.f32 "
        "{%0,%1,%2,%3}, {%4,%5,%6,%7}, {%8,%9}, {%0,%1,%2,%3};\n"
        : "+f"(c[0]), "+f"(c[1]), "+f"(c[2]), "+f"(c[3])
        : "r"(a[0]), "r"(a[1]), "r"(a[2]), "r"(a[3]), "r"(b0), "r"(b1));
}

__device__ __forceinline__ float tanhA(float x) {
    float y;
    asm("tanh.approx.f32 %0, %1;" : "=f"(y) : "f"(x));
    return y;
}
__device__ __forceinline__ float sigmoid_fast(float x) {
    return __fdividef(1.0f, 1.0f + __expf(-x));
}
__device__ __forceinline__ float tanh_fast(float x) {
    x = fminf(15.0f, fmaxf(-15.0f, x));
    float e = __expf(2.0f * x);
    return 1.0f - __fdividef(2.0f, e + 1.0f);
}

__device__ __forceinline__ float warpMax(float v) {
    #pragma unroll
    for (int o = 16; o; o >>= 1) v = fmaxf(v, __shfl_xor_sync(0xffffffffu, v, o));
    return v;
}
__device__ __forceinline__ float warpSum(float v) {
    #pragma unroll
    for (int o = 16; o; o >>= 1) v += __shfl_xor_sync(0xffffffffu, v, o);
    return v;
}
__device__ __forceinline__ float blockMax(float v, float* red) {
    v = warpMax(v);
    int w = threadIdx.x >> 5, l = threadIdx.x & 31, nw = blockDim.x >> 5;
    if (l == 0) red[w] = v;
    __syncthreads();
    if (threadIdx.x < 32) {
        float x = (threadIdx.x < nw) ? red[threadIdx.x] : -INFINITY;
        x = warpMax(x);
        if (threadIdx.x == 0) red[0] = x;
    }
    __syncthreads();
    v = red[0];
    __syncthreads();
    return v;
}
__device__ __forceinline__ float blockSum(float v, float* red) {
    v = warpSum(v);
    int w = threadIdx.x >> 5, l = threadIdx.x & 31, nw = blockDim.x >> 5;
    if (l == 0) red[w] = v;
    __syncthreads();
    if (threadIdx.x < 32) {
        float x = (threadIdx.x < nw) ? red[threadIdx.x] : 0.0f;
        x = warpSum(x);
        if (threadIdx.x == 0) red[0] = x;
    }
    __syncthreads();
    v = red[0];
    __syncthreads();
    return v;
}

// ---------------------------------------------------------------------------
// Convert/repack fp32 -> fp16 with optional column slice + zero padding
// ---------------------------------------------------------------------------
__global__ void cvt_pad(const float* __restrict__ src, __half* __restrict__ dst,
                        int rows, int sstr, int soff, int dstr, int clen)
{
    int total = rows * dstr;
    for (int i = blockIdx.x * blockDim.x + threadIdx.x; i < total;
         i += gridDim.x * blockDim.x) {
        int r = i / dstr, c = i - r * dstr;
        float v = (c < clen) ? src[(size_t)r * sstr + soff + c] : 0.0f;
        dst[i] = __float2half(v);
    }
}

// ---------------------------------------------------------------------------
// fp16 tensor-core GEMM: C[M,N] = A[M,K] @ W[N,K]^T
// block tile 64x64, K-chunk 32, 128 threads (4 warps, 2x2, warp tile 32x32)
// ---------------------------------------------------------------------------
struct GH {
    const __half* A; int lda;       // MODE_PLAIN
    const __half* W; int ldw;
    float* C; int ldc;
    int N;
    int K;                          // K per split (multiple of 32)
    int kbeg, kend;                 // absolute column range [kbeg, kend)
    const __half* embed;            // MODE_EMB
    const int*    tgt;
    const __half* ctx;              // MODE_CS
    const __half* s;
};

#define MODE_PLAIN 0
#define MODE_EMB   1   // A row m -> embed_h[word(t=m>>7, b=m&127)]
#define MODE_CS    2   // A = [ctx(512) | s(512)]

template <int MODE, bool OUTH>
__device__ __forceinline__ void grun(const GH& g) {
    extern __shared__ __half smh[];
    __half* As = smh;
    __half* Ws = smh + STAGES * 64 * SK;

    const int tid = threadIdx.x, lane = tid & 31, warp = tid >> 5;
    const int wm = warp >> 1, wn = warp & 1;
    const int mt0 = blockIdx.y * 64, nt0 = blockIdx.x * 64;

    const int r0 = tid >> 2, kc = (tid & 3) * 8;
    const int r1 = r0 + 32;
    const int gm0 = mt0 + r0, gm1 = mt0 + r1;
    const int gn0 = nt0 + r0, gn1 = nt0 + r1;

    const __half *a0 = nullptr, *a1 = nullptr;
    const __half *c0p = nullptr, *c1p = nullptr, *s0p = nullptr, *s1p = nullptr;
    if (MODE == MODE_PLAIN) {
        a0 = g.A + (size_t)gm0 * g.lda;
        a1 = g.A + (size_t)gm1 * g.lda;
    } else if (MODE == MODE_EMB) {
        int t0 = gm0 >> 7, b0 = gm0 & 127;
        int w0 = (t0 == 0) ? SOS_ID : g.tgt[b0 * TT + t0 - 1];
        if (w0 >= VV) w0 = UNK_ID;
        int t1 = gm1 >> 7, b1 = gm1 & 127;
        int w1 = (t1 == 0) ? SOS_ID : g.tgt[b1 * TT + t1 - 1];
        if (w1 >= VV) w1 = UNK_ID;
        a0 = g.embed + (size_t)w0 * 304;
        a1 = g.embed + (size_t)w1 * 304;
    } else {
        c0p = g.ctx + gm0 * 512; c1p = g.ctx + gm1 * 512;
        s0p = g.s   + gm0 * 512; s1p = g.s   + gm1 * 512;
    }
    const bool n0ok = (gn0 < g.N), n1ok = (gn1 < g.N);
    const __half* w0p = g.W + (size_t)(n0ok ? gn0 : 0) * g.ldw;
    const __half* w1p = g.W + (size_t)(n1ok ? gn1 : 0) * g.ldw;

    const uint32_t asB = (uint32_t)__cvta_generic_to_shared(As);
    const uint32_t wsB = (uint32_t)__cvta_generic_to_shared(Ws);
    const int STB = 64 * SK * 2;
    const uint32_t aD0 = asB + (r0 * SK + kc) * 2;
    const uint32_t aD1 = asB + (r1 * SK + kc) * 2;
    const uint32_t wD0 = wsB + (r0 * SK + kc) * 2;
    const uint32_t wD1 = wsB + (r1 * SK + kc) * 2;

    const int nk = (g.kend - g.kbeg + 31) >> 5;

    auto pf = [&](int i) {
        int kg = g.kbeg + i * 32 + kc;
        int buf = (i & 3) * STB;
        bool v = kg < g.kend;
        const __half *sa0, *sa1;
        if (MODE == MODE_CS) {
            sa0 = (kg < 512) ? c0p + kg : s0p + (kg - 512);
            sa1 = (kg < 512) ? c1p + kg : s1p + (kg - 512);
        } else {
            sa0 = a0 + kg; sa1 = a1 + kg;
        }
        if (!v) { sa0 = g.W; sa1 = g.W; }
        cp_async16(aD0 + buf, sa0, v ? 16 : 0);
        cp_async16(aD1 + buf, sa1, v ? 16 : 0);
        bool v0 = v && n0ok, v1 = v && n1ok;
        cp_async16(wD0 + buf, v0 ? (w0p + kg) : g.W, v0 ? 16 : 0);
        cp_async16(wD1 + buf, v1 ? (w1p + kg) : g.W, v1 ? 16 : 0);
    };

    #pragma unroll
    for (int p = 0; p < 3; p++) {
        if (p < nk) pf(p);
        cp_commit();
    }

    float c[2][4][4] = {};
    const int lr = lane & 15, lk = (lane >> 4) * 8;

    for (int i = 0; i < nk; i++) {
        if (i + 3 < nk) pf(i + 3);
        cp_commit();
        cp_wait<3>();
        __syncthreads();

        const uint32_t ab = asB + (i & 3) * STB;
        const uint32_t wb = wsB + (i & 3) * STB;

        #pragma unroll
        for (int kk = 0; kk < 32; kk += 16) {
            uint32_t a[2][4], bb[2][4];
            #pragma unroll
            for (int mt = 0; mt < 2; mt++)
                ldsm4(a[mt], ab + ((wm * 32 + mt * 16 + lr) * SK + kk + lk) * 2);
            #pragma unroll
            for (int n2 = 0; n2 < 2; n2++)
                ldsm4(bb[n2], wb + ((wn * 32 + n2 * 16 + lr) * SK + kk + lk) * 2);
            #pragma unroll
            for (int mt = 0; mt < 2; mt++)
                #pragma unroll
                for (int ns = 0; ns < 4; ns++) {
                    int n2 = ns >> 1, sel = ns & 1;
                    mma_f16(c[mt][ns], a[mt], bb[n2][sel], bb[n2][sel + 2]);
                }
        }
        __syncthreads();
    }

    // Epilogue
    const int gr = lane >> 2, gc = (lane & 3) * 2;
    #pragma unroll
    for (int mt = 0; mt < 2; mt++)
        #pragma unroll
        for (int ns = 0; ns < 4; ns++) {
            int row = mt0 + wm * 32 + mt * 16 + gr;
            int col = nt0 + wn * 32 + ns * 8 + gc;
            if (col < g.N) {
                if (OUTH) {
                    __half* Ch = (__half*)g.C;
                    Ch[(size_t)row * g.ldc + col]           = __float2half(c[mt][ns][0]);
                    Ch[(size_t)row * g.ldc + col + 1]       = __float2half(c[mt][ns][1]);
                    Ch[(size_t)(row + 8) * g.ldc + col]     = __float2half(c[mt][ns][2]);
                    Ch[(size_t)(row + 8) * g.ldc + col + 1] = __float2half(c[mt][ns][3]);
                } else {
                    g.C[(size_t)row * g.ldc + col]           = c[mt][ns][0];
                    g.C[(size_t)row * g.ldc + col + 1]       = c[mt][ns][1];
                    g.C[(size_t)(row + 8) * g.ldc + col]     = c[mt][ns][2];
                    g.C[(size_t)(row + 8) * g.ldc + col + 1] = c[mt][ns][3];
                }
            }
        }
}

__global__ __launch_bounds__(128) void k_g_plain(GH g)   { grun<MODE_PLAIN, false>(g); }
__global__ __launch_bounds__(128) void k_g_plain_h(GH g) { grun<MODE_PLAIN, true >(g); }
__global__ __launch_bounds__(128) void k_g_emb(GH g)     { grun<MODE_EMB,   false>(g); }
__global__ __launch_bounds__(128) void k_g_plain_split(GH g) {
    int sp = blockIdx.z;
    g.kbeg = sp * g.K; g.kend = g.kbeg + g.K;
    g.C += (size_t)sp * BB * g.ldc;
    grun<MODE_PLAIN, false>(g);
}
__global__ __launch_bounds__(128) void k_g_cs_split(GH g) {
    int sp = blockIdx.z;
    g.kbeg = sp * g.K; g.kend = g.kbeg + g.K;
    g.C += (size_t)sp * BB * g.ldc;
    grun<MODE_CS, false>(g);
}
__global__ __launch_bounds__(128) void k_gates(GH gi, GH gh) {
    int z = blockIdx.z;
    GH g = (z < 4) ? gi : gh;
    int sp = z & 3;
    g.kbeg = sp * g.K; g.kend = g.kbeg + g.K;
    g.C += (size_t)sp * BB * g.ldc;
    grun<MODE_PLAIN, false>(g);
}

// ---------------------------------------------------------------------------
// GRU: reduce split-K partials + precomputed emb part, then gate math
// ---------------------------------------------------------------------------
__global__ __launch_bounds__(256) void gru_kernel(
    const float* __restrict__ gip, const float* __restrict__ ghp,
    const float* __restrict__ giemb,
    const float* __restrict__ b_ih, const float* __restrict__ b_hh,
    const float* __restrict__ s_old,
    float* __restrict__ s_new, __half* __restrict__ s_h, int t)
{
    int idx = blockIdx.x * blockDim.x + threadIdx.x;   // BB*HD
    int b = idx >> 9, h = idx & 511;
    size_t ob = (size_t)b * 1536;
    size_t oe = ((size_t)t * BB + b) * 1536;

    float ir = giemb[oe + h]            + b_ih[h];
    float iz = giemb[oe + HD + h]       + b_ih[HD + h];
    float in = giemb[oe + 2 * HD + h]   + b_ih[2 * HD + h];
    float hr = b_hh[h], hz = b_hh[HD + h], hn = b_hh[2 * HD + h];
    #pragma unroll
    for (int z = 0; z < 4; z++) {
        size_t o = (size_t)z * BB * 1536 + ob;
        ir += gip[o + h];      iz += gip[o + HD + h];  in += gip[o + 2 * HD + h];
        hr += ghp[o + h];      hz += ghp[o + HD + h];  hn += ghp[o + 2 * HD + h];
    }
    float r = sigmoid_fast(ir + hr);
    float z = sigmoid_fast(iz + hz);
    float n = tanh_fast(in + r * hn);
    float so = s_old[idx];
    float sn = (1.0f - z) * n + z * so;
    s_new[idx] = sn;
    s_h[idx] = __float2half(sn);
}

// ---------------------------------------------------------------------------
// Fused attention (fp16 tables): q-reduce -> e -> softmax -> ctx -> p_copy
// ---------------------------------------------------------------------------
__global__ __launch_bounds__(512) void attn_kernel(
    const float* __restrict__ qp,      // [4][B][512] partials
    const float* __restrict__ att_b,
    const __half* __restrict__ proj,   // [B,L,A] fp16
    const __half* __restrict__ ench,   // [B,L,HE] fp16
    const float* __restrict__ vvec,
    const int*   __restrict__ src,
    const float* __restrict__ s_new,
    const float* __restrict__ copy_W,
    const float* __restrict__ copy_b,
    float* __restrict__ attn_out,
    __half* __restrict__ ctx_h,
    float* __restrict__ pc_out)
{
    __shared__ __align__(16) float es[LL];
    __shared__ float part[2][HE];
    __shared__ float red[32];

    int b = blockIdx.x, tid = threadIdx.x;
    int warp = tid >> 5, lane = tid & 31;

    float qf[2][8], vf[2][8];
    #pragma unroll
    for (int j = 0; j < 2; j++) {
        int base = (lane + 32 * j) * 8;
        float4 b0 = *(const float4*)(att_b + base);
        float4 b1 = *(const float4*)(att_b + base + 4);
        qf[j][0] = b0.x; qf[j][1] = b0.y; qf[j][2] = b0.z; qf[j][3] = b0.w;
        qf[j][4] = b1.x; qf[j][5] = b1.y; qf[j][6] = b1.z; qf[j][7] = b1.w;
        #pragma unroll
        for (int z = 0; z < 4; z++) {
            const float* qz = qp + ((size_t)z * BB + b) * 512 + base;
            float4 q0 = *(const float4*)qz;
            float4 q1 = *(const float4*)(qz + 4);
            qf[j][0] += q0.x; qf[j][1] += q0.y; qf[j][2] += q0.z; qf[j][3] += q0.w;
            qf[j][4] += q1.x; qf[j][5] += q1.y; qf[j][6] += q1.z; qf[j][7] += q1.w;
        }
        float4 v0 = *(const float4*)(vvec + base);
        float4 v1 = *(const float4*)(vvec + base + 4);
        vf[j][0] = v0.x; vf[j][1] = v0.y; vf[j][2] = v0.z; vf[j][3] = v0.w;
        vf[j][4] = v1.x; vf[j][5] = v1.y; vf[j][6] = v1.z; vf[j][7] = v1.w;
    }

    // Phase 1: scores
    for (int l = warp; l < LL; l += 16) {
        const uint4* pp = (const uint4*)(proj + ((size_t)b * LL + l) * AA);
        float acc = 0.0f;
        #pragma unroll
        for (int j = 0; j < 2; j++) {
            uint4 pv = pp[lane + 32 * j];
            const __half2* h2 = (const __half2*)&pv;
            #pragma unroll
            for (int p = 0; p < 4; p++) {
                float2 f = __half22float2(h2[p]);
                acc += tanhA(f.x + qf[j][2 * p])     * vf[j][2 * p];
                acc += tanhA(f.y + qf[j][2 * p + 1]) * vf[j][2 * p + 1];
            }
        }
        acc = warpSum(acc);
        if (lane == 0)
            es[l] = (src[b * LL + l] == PAD_ID) ? -1e30f : acc;
    }
    __syncthreads();

    // Phase 2: softmax over L
    float ev = (tid < LL) ? es[tid] : -INFINITY;
    float m  = blockMax(ev, red);
    float p  = (tid < LL) ? __expf(ev - m) : 0.0f;
    float Z  = blockSum(p, red);
    float a  = p / Z;
    if (tid < LL) { es[tid] = a; attn_out[b * LL + tid] = a; }
    __syncthreads();

    // Phase 3: ctx via fp16 enc, 2 L-groups x 256 column-pairs
    int gg = tid >> 8, cc = tid & 255;
    const __half2* eb = (const __half2*)(ench + (size_t)b * LL * HE) + cc;
    float ax = 0.0f, ay = 0.0f;
    int l0 = gg * 200;
    #pragma unroll 4
    for (int l = l0; l < l0 + 200; l++) {
        float2 f = __half22float2(eb[(size_t)l * 256]);
        ax += es[l] * f.x;
        ay += es[l] * f.y;
    }
    part[gg][2 * cc]     = ax;
    part[gg][2 * cc + 1] = ay;
    __syncthreads();

    float ctxv = part[0][tid] + part[1][tid];
    ctx_h[b * HE + tid] = __float2half(ctxv);

    // Phase 4: p_copy
    float pp_ = s_new[b * HD + tid] * copy_W[tid] + ctxv * copy_W[HD + tid];
    float tot = blockSum(pp_, red);
    if (tid == 0) pc_out[b] = sigmoid_fast(tot + copy_b[0]);
}

// ---------------------------------------------------------------------------
// Maxout reduce: m = maxout(sum rv partials + rvemb + bias) -> fp16
// ---------------------------------------------------------------------------
__global__ __launch_bounds__(256) void mred_kernel(
    const float* __restrict__ rvp, const float* __restrict__ rvemb,
    const float* __restrict__ read_b, __half* __restrict__ mh, int t)
{
    int idx = blockIdx.x * blockDim.x + threadIdx.x;   // BB*256
    int b = idx >> 8, c = idx & 255;
    int h0 = 2 * c, h1 = 2 * c + 1;
    size_t oe = ((size_t)t * BB + b) * 512;
    float r0 = rvemb[oe + h0] + read_b[h0];
    float r1 = rvemb[oe + h1] + read_b[h1];
    #pragma unroll
    for (int z = 0; z < 4; z++) {
        size_t o = (size_t)z * BB * 512 + (size_t)b * 512;
        r0 += rvp[o + h0];
        r1 += rvp[o + h1];
    }
    mh[idx] = __float2half(fmaxf(r0, r1));
}

// ---------------------------------------------------------------------------
// Output: softmax over V, log of [(1-pc)*p_vocab, pc*attn] + 1e-12
// ---------------------------------------------------------------------------
__global__ __launch_bounds__(1024) void output_kernel(
    const float* __restrict__ energy,
    const float* __restrict__ attn,
    const float* __restrict__ pc_in,
    float* __restrict__ out, int t)
{
    __shared__ float red[32];
    int b = blockIdx.x, tid = threadIdx.x;
    const float4* eb4 = (const float4*)(energy + (size_t)b * VV);

    float mx = -INFINITY;
    for (int j = tid; j < VV / 4; j += 1024) {
        float4 v = eb4[j];
        mx = fmaxf(mx, fmaxf(fmaxf(v.x, v.y), fmaxf(v.z, v.w)));
    }
    mx = blockMax(mx, red);

    float sm = 0.0f;
    for (int j = tid; j < VV / 4; j += 1024) {
        float4 v = eb4[j];
        sm += __expf(v.x - mx) + __expf(v.y - mx) + __expf(v.z - mx) + __expf(v.w - mx);
    }
    sm = blockSum(sm, red);

    float pc = pc_in[b];
    float scale = (1.0f - pc) / sm;
    float* ob = out + ((size_t)b * TT + t) * (VV + LL);
    float4* ob4 = (float4*)ob;
    for (int j = tid; j < VV / 4; j += 1024) {
        float4 v = eb4[j], o;
        o.x = __logf(__expf(v.x - mx) * scale + 1e-12f);
        o.y = __logf(__expf(v.y - mx) * scale + 1e-12f);
        o.z = __logf(__expf(v.z - mx) * scale + 1e-12f);
        o.w = __logf(__expf(v.w - mx) * scale + 1e-12f);
        ob4[j] = o;
    }
    const float4* at4 = (const float4*)(attn + (size_t)b * LL);
    float4* oc4 = (float4*)(ob + VV);
    for (int j = tid; j < LL / 4; j += 1024) {
        float4 a = at4[j], o;
        o.x = __logf(fmaf(pc, a.x, 1e-12f));
        o.y = __logf(fmaf(pc, a.y, 1e-12f));
        o.z = __logf(fmaf(pc, a.z, 1e-12f));
        o.w = __logf(fmaf(pc, a.w, 1e-12f));
        oc4[j] = o;
    }
}

// ---------------------------------------------------------------------------
// Host orchestration: critical chain on stream 0, output tail on side stream
// ---------------------------------------------------------------------------
static inline void cvt(const float* s, __half* d, int rows, int sstr, int soff,
                       int dstr, int clen) {
    int total = rows * dstr;
    int grid = (total + 255) / 256;
    if (grid > 8192) grid = 8192;
    cvt_pad<<<grid, 256>>>(s, d, rows, sstr, soff, dstr, clen);
}

extern "C" void kernel_launch(void* const* d_in, const int* in_sizes, int n_in,
                              void* d_out, int out_size)
{
    const float* enc     = (const float*)d_in[0];
    const float* s_in    = (const float*)d_in[1];
    const int*   src     = (const int*)  d_in[2];
    const int*   tgt     = (const int*)  d_in[3];
    const float* embed   = (const float*)d_in[4];
    const float* W_ih    = (const float*)d_in[5];
    const float* b_ih    = (const float*)d_in[6];
    const float* W_hh    = (const float*)d_in[7];
    const float* b_hh    = (const float*)d_in[8];
    const float* att_Wh  = (const float*)d_in[9];
    const float* att_Ws  = (const float*)d_in[10];
    const float* att_b   = (const float*)d_in[11];
    const float* att_v   = (const float*)d_in[12];
    const float* copy_W  = (const float*)d_in[13];
    const float* copy_b  = (const float*)d_in[14];
    const float* read_W  = (const float*)d_in[15];
    const float* read_b  = (const float*)d_in[16];
    const float* read_Wo = (const float*)d_in[17];
    float* out = (float*)d_out;

    __half *p_ench, *p_projh, *p_embh, *p_Wihe, *p_Wihc, *p_Whh, *p_Ws, *p_Wh;
    __half *p_Wre, *p_Wrc, *p_Wo, *p_shh, *p_chh, *p_mh;
    float *p_giemb, *p_rvemb, *p_gip, *p_ghp, *p_qp, *p_rvp;
    float *p_sf, *p_attn, *p_pc, *p_energy;

    cudaGetSymbolAddress((void**)&p_ench,  g_enc_h);
    cudaGetSymbolAddress((void**)&p_projh, g_proj_h);
    cudaGetSymbolAddress((void**)&p_embh,  g_embed_h);
    cudaGetSymbolAddress((void**)&p_Wihe,  g_Wih_e);
    cudaGetSymbolAddress((void**)&p_Wihc,  g_Wih_c);
    cudaGetSymbolAddress((void**)&p_Whh,   g_Whh);
    cudaGetSymbolAddress((void**)&p_Ws,    g_Ws);
    cudaGetSymbolAddress((void**)&p_Wh,    g_Wh);
    cudaGetSymbolAddress((void**)&p_Wre,   g_Wr_e);
    cudaGetSymbolAddress((void**)&p_Wrc,   g_Wr_c);
    cudaGetSymbolAddress((void**)&p_Wo,    g_Wo);
    cudaGetSymbolAddress((void**)&p_giemb, g_giemb);
    cudaGetSymbolAddress((void**)&p_rvemb, g_rvemb);
    cudaGetSymbolAddress((void**)&p_gip,   g_gi_p);
    cudaGetSymbolAddress((void**)&p_ghp,   g_gh_p);
    cudaGetSymbolAddress((void**)&p_qp,    g_q_p);
    cudaGetSymbolAddress((void**)&p_rvp,   g_rv_p);
    cudaGetSymbolAddress((void**)&p_sf,    g_sf);
    cudaGetSymbolAddress((void**)&p_shh,   g_shh);
    cudaGetSymbolAddress((void**)&p_chh,   g_chh);
    cudaGetSymbolAddress((void**)&p_mh,    g_mh);
    cudaGetSymbolAddress((void**)&p_attn,  g_attnb);
    cudaGetSymbolAddress((void**)&p_pc,    g_pcb);
    cudaGetSymbolAddress((void**)&p_energy,g_energy);

    // Side stream + events for the output tail (created per call; handles are
    // host-side and intentionally not destroyed mid-capture).
    cudaStream_t side;
    cudaStreamCreateWithFlags(&side, cudaStreamNonBlocking);
    cudaEvent_t evF[TT], evJ;
    for (int t = 0; t < TT; t++)
        cudaEventCreateWithFlags(&evF[t], cudaEventDisableTiming);
    cudaEventCreateWithFlags(&evJ, cudaEventDisableTiming);

    // ---- Precompute: conversions / repacks (stream 0) ----
    cvt(enc,     p_ench, BB * LL, HE, 0, HE, HE);
    cvt(embed,   p_embh, VV, EE, 0, 304, EE);
    cvt(W_ih,    p_Wihe, 1536, 812, 0, 304, 300);
    cvt(W_ih,    p_Wihc, 1536, 812, 300, 512, 512);
    cvt(W_hh,    p_Whh,  1536, 512, 0, 512, 512);
    cvt(att_Ws,  p_Ws,   512, 512, 0, 512, 512);
    cvt(att_Wh,  p_Wh,   512, 512, 0, 512, 512);
    cvt(read_W,  p_Wre,  512, 1324, 0, 304, 300);
    cvt(read_W,  p_Wrc,  512, 1324, 300, 1024, 1024);
    cvt(read_Wo, p_Wo,   VV, 256, 0, 256, 256);
    cvt(s_in,    p_shh,  BB, HD, 0, HD, HD);     // slot 0

    cudaMemcpyAsync(p_sf, s_in, BB * HD * sizeof(float),
                    cudaMemcpyDeviceToDevice, 0);
    cudaMemsetAsync(p_chh, 0, BB * HE * sizeof(__half), 0);   // ctx slot 0

    // ---- Precompute: big GEMMs ----
    {   // proj = enc @ att_Wh^T -> fp16
        GH g{}; g.A = p_ench; g.lda = HE; g.W = p_Wh; g.ldw = 512;
        g.C = (float*)p_projh; g.ldc = AA; g.N = AA;
        g.kbeg = 0; g.kend = 512;
        k_g_plain_h<<<dim3(8, 800), 128, SMEM_GEMM>>>(g);
    }
    {   // giemb[all t] = emb @ Wih_e^T
        GH g{}; g.embed = p_embh; g.tgt = tgt; g.W = p_Wihe; g.ldw = 304;
        g.C = p_giemb; g.ldc = 1536; g.N = 1536;
        g.kbeg = 0; g.kend = 304;
        k_g_emb<<<dim3(24, 60), 128, SMEM_GEMM>>>(g);
    }
    {   // rvemb[all t] = emb @ Wr_e^T
        GH g{}; g.embed = p_embh; g.tgt = tgt; g.W = p_Wre; g.ldw = 304;
        g.C = p_rvemb; g.ldc = 512; g.N = 512;
        g.kbeg = 0; g.kend = 304;
        k_g_emb<<<dim3(8, 60), 128, SMEM_GEMM>>>(g);
    }

    for (int t = 0; t < TT; t++) {
        // Per-step ring slots
        float*  sCur = p_sf  + (size_t)t * BB * HD;
        float*  sNxt = p_sf  + (size_t)(t + 1) * BB * HD;
        __half* shC  = p_shh + (size_t)t * BB * HD;
        __half* shN  = p_shh + (size_t)(t + 1) * BB * HD;
        __half* chC  = p_chh + (size_t)t * BB * HE;
        __half* chN  = p_chh + (size_t)(t + 1) * BB * HE;
        float*  atT  = p_attn + (size_t)t * BB * LL;
        float*  pcT  = p_pc + (size_t)t * BB;

        // ---- Critical chain (stream 0) ----
        {   // gi_ctx (splitK4) + gh (splitK4), fused launch
            GH gi{}; gi.A = chC; gi.lda = 512; gi.W = p_Wihc; gi.ldw = 512;
            gi.C = p_gip; gi.ldc = 1536; gi.N = 1536; gi.K = 128;
            GH gh{}; gh.A = shC; gh.lda = 512; gh.W = p_Whh; gh.ldw = 512;
            gh.C = p_ghp; gh.ldc = 1536; gh.N = 1536; gh.K = 128;
            k_gates<<<dim3(24, 2, 8), 128, SMEM_GEMM>>>(gi, gh);
        }
        gru_kernel<<<(BB * HD) / 256, 256>>>(p_gip, p_ghp, p_giemb,
                                             b_ih, b_hh, sCur, sNxt, shN, t);
        {   // q partials = s_new @ att_Ws^T (splitK4)
            GH g{}; g.A = shN; g.lda = 512; g.W = p_Ws; g.ldw = 512;
            g.C = p_qp; g.ldc = 512; g.N = 512; g.K = 128;
            k_g_plain_split<<<dim3(8, 2, 4), 128, SMEM_GEMM>>>(g);
        }
        attn_kernel<<<BB, 512>>>(p_qp, att_b, p_projh, p_ench, att_v, src,
                                 sNxt, copy_W, copy_b, atT, chN, pcT);

        // ---- Fork the output tail onto the side stream ----
        cudaEventRecord(evF[t], 0);
        cudaStreamWaitEvent(side, evF[t], 0);

        {   // rvec partials = [ctx_new, s_new] @ Wr_c^T (splitK4)
            GH g{}; g.ctx = chN; g.s = shN; g.W = p_Wrc; g.ldw = 1024;
            g.C = p_rvp; g.ldc = 512; g.N = 512; g.K = 256;
            k_g_cs_split<<<dim3(8, 2, 4), 128, SMEM_GEMM, side>>>(g);
        }
        mred_kernel<<<BB, 256, 0, side>>>(p_rvp, p_rvemb, read_b, p_mh, t);
        {   // energy = m @ read_Wo^T
            GH g{}; g.A = p_mh; g.lda = 256; g.W = p_Wo; g.ldw = 256;
            g.C = p_energy; g.ldc = VV; g.N = VV;
            g.kbeg = 0; g.kend = 256;
            k_g_plain<<<dim3(313, 2), 128, SMEM_GEMM, side>>>(g);
        }
        output_kernel<<<BB, 1024, 0, side>>>(p_energy, atT, pcT, out, t);
    }

    // ---- Join side stream back before returning (capture must be joined) ----
    cudaEventRecord(evJ, side);
    cudaStreamWaitEvent(0, evJ, 0);
}